// round 13
// baseline (speedup 1.0000x reference)
#include <cuda_runtime.h>
#include <stdint.h>
#include <math.h>

#define L 512
#define D 128
#define NH 4
#define CC 32
#define M_ROWS (L * L)          // 262144
#define R_DIM (L * CC)          // 16384
#define LL (L * L)

// ---------------- scratch ----------------------------------------------------
__device__ float g_z[M_ROWS * D];        // post-LN z (tf32-rounded)
__device__ float g_qm[NH * L * R_DIM];   // q [h][l][bc] tf32 (m-major)
__device__ float g_kT[NH * R_DIM * L];   // k [h][bc][l] tf32 (k-major)
__device__ float g_vt[NH * L * R_DIM];   // v [h][k2][bc] tf32
__device__ float g_sig[M_ROWS * D];      // sigmoid gate
__device__ float g_bias[M_ROWS * NH];    // [(l*512+k), h]
__device__ float g_part[16 * LL];        // [h*4+sk][l][k] split-K partials
__device__ float g_att[NH * LL];         // softmax probs tf32
__device__ float g_o[NH * L * R_DIM];    // gated o tf32
__device__ float g_wq[D * D], g_wk[D * D], g_wv[D * D], g_wg[D * D], g_wo[D * D];

// ---------------- helpers ----------------------------------------------------
__device__ __forceinline__ unsigned tf32c(float x) {
    unsigned u; asm("cvt.rna.tf32.f32 %0, %1;" : "=r"(u) : "f"(x)); return u;
}
__device__ __forceinline__ float tf32f(float x) { return __uint_as_float(tf32c(x)); }

__device__ __forceinline__ void mma8(float* c, const unsigned* a, const unsigned* b) {
    asm volatile(
        "mma.sync.aligned.m16n8k8.row.col.f32.tf32.tf32.f32 "
        "{%0,%1,%2,%3},{%4,%5,%6,%7},{%8,%9},{%0,%1,%2,%3};"
        : "+f"(c[0]), "+f"(c[1]), "+f"(c[2]), "+f"(c[3])
        : "r"(a[0]), "r"(a[1]), "r"(a[2]), "r"(a[3]), "r"(b[0]), "r"(b[1]));
}

__device__ __forceinline__ void cpa16(uint32_t dst, const float* src) {
    asm volatile("cp.async.cg.shared.global [%0], [%1], 16;\n" :: "r"(dst), "l"(src));
}
__device__ __forceinline__ void cpa_commit() { asm volatile("cp.async.commit_group;\n"); }
template <int N> __device__ __forceinline__ void cpa_wait() {
    asm volatile("cp.async.wait_group %0;\n" :: "n"(N));
}
__device__ __forceinline__ uint32_t sa(const void* p) {
    return (uint32_t)__cvta_generic_to_shared(p);
}

// ---- tile loaders ----
__device__ __forceinline__ void cpa_A32(float (*S)[36], const float* src, size_t ld, int tid) {
    #pragma unroll
    for (int p = 0; p < 4; p++) {
        int idx = p * 256 + tid;
        int row = idx >> 3, c4 = (idx & 7) * 4;
        cpa16(sa(&S[row][c4]), src + (size_t)row * ld + c4);
    }
}
__device__ __forceinline__ void cpa_B32(float (*S)[136], const float* src, size_t ld, int tid) {
    #pragma unroll
    for (int p = 0; p < 4; p++) {
        int idx = p * 256 + tid;
        int r = idx >> 5, c4 = (idx & 31) * 4;
        cpa16(sa(&S[r][c4]), src + (size_t)r * ld + c4);
    }
}
__device__ __forceinline__ void cpa_B256(float (*S)[264], const float* src, size_t ld, int tid) {
    #pragma unroll
    for (int p = 0; p < 8; p++) {
        int idx = p * 256 + tid;
        int r = idx >> 6, c4 = (idx & 63) * 4;
        cpa16(sa(&S[r][c4]), src + (size_t)r * ld + c4);
    }
}

// ---- compute: 64x32 warp tile ----
__device__ __forceinline__ void comp32(const float (*Am)[36], const float (*Bs)[136],
                                       float acc[4][4][4], int wr, int wc, int lane) {
    int t = lane & 3, g = lane >> 2;
    #pragma unroll
    for (int ks = 0; ks < 32; ks += 8) {
        unsigned a[4][4], b[4][2];
        #pragma unroll
        for (int mi = 0; mi < 4; mi++) {
            int r = wr * 64 + mi * 16 + g;
            a[mi][0] = __float_as_uint(Am[r][ks + t]);
            a[mi][1] = __float_as_uint(Am[r + 8][ks + t]);
            a[mi][2] = __float_as_uint(Am[r][ks + t + 4]);
            a[mi][3] = __float_as_uint(Am[r + 8][ks + t + 4]);
        }
        #pragma unroll
        for (int ni = 0; ni < 4; ni++) {
            int c = wc * 32 + ni * 8 + g;
            b[ni][0] = __float_as_uint(Bs[ks + t][c]);
            b[ni][1] = __float_as_uint(Bs[ks + t + 4][c]);
        }
        #pragma unroll
        for (int mi = 0; mi < 4; mi++)
            #pragma unroll
            for (int ni = 0; ni < 4; ni++) mma8(acc[mi][ni], a[mi], b[ni]);
    }
}

// ---- compute: 64x64 warp tile ----
__device__ __forceinline__ void comp_w64(const float (*Am)[36], const float (*Bs)[264],
                                         float acc[4][8][4], int wrow, int wcol, int lane) {
    int t = lane & 3, g = lane >> 2;
    #pragma unroll
    for (int ks = 0; ks < 32; ks += 8) {
        unsigned a[4][4], b[8][2];
        #pragma unroll
        for (int mi = 0; mi < 4; mi++) {
            int r = wrow * 64 + mi * 16 + g;
            a[mi][0] = __float_as_uint(Am[r][ks + t]);
            a[mi][1] = __float_as_uint(Am[r + 8][ks + t]);
            a[mi][2] = __float_as_uint(Am[r][ks + t + 4]);
            a[mi][3] = __float_as_uint(Am[r + 8][ks + t + 4]);
        }
        #pragma unroll
        for (int ni = 0; ni < 8; ni++) {
            int c = wcol * 64 + ni * 8 + g;
            b[ni][0] = __float_as_uint(Bs[ks + t][c]);
            b[ni][1] = __float_as_uint(Bs[ks + t + 4][c]);
        }
        #pragma unroll
        for (int mi = 0; mi < 4; mi++)
            #pragma unroll
            for (int ni = 0; ni < 8; ni++) mma8(acc[mi][ni], a[mi], b[ni]);
    }
}

#define DYN_STD  ((3 * 128 * 36 + 3 * 32 * 136) * 4)   // 107520
#define DYN_ATT4 ((4 * 128 * 36 + 4 * 32 * 264) * 4)   // 208896

// ---------------- small kernels ----------------------------------------------
__global__ void round_w(const float* __restrict__ qw, const float* __restrict__ kw,
                        const float* __restrict__ vw, const float* __restrict__ gw,
                        const float* __restrict__ ow) {
    int i = blockIdx.x * 256 + threadIdx.x;
    if (i >= D * D) return;
    g_wq[i] = tf32f(qw[i]); g_wk[i] = tf32f(kw[i]);
    g_wv[i] = tf32f(vw[i]); g_wg[i] = tf32f(gw[i]);
    g_wo[i] = tf32f(ow[i]);
}

// fused LN (writes tf32 g_z) + bias projection, one pass over z_
__global__ void ln_bias_kernel(const float* __restrict__ zin,
                               const float* __restrict__ gamma,
                               const float* __restrict__ beta,
                               const float* __restrict__ bw,
                               const float* __restrict__ bb) {
    int warp = (blockIdx.x * blockDim.x + threadIdx.x) >> 5;
    int lane = threadIdx.x & 31;
    if (warp >= M_ROWS) return;
    float4 x = ((const float4*)(zin + (size_t)warp * D))[lane];
    float s = x.x + x.y + x.z + x.w;
    float ss = x.x * x.x + x.y * x.y + x.z * x.z + x.w * x.w;
    #pragma unroll
    for (int o = 16; o; o >>= 1) {
        s += __shfl_xor_sync(0xffffffffu, s, o);
        ss += __shfl_xor_sync(0xffffffffu, ss, o);
    }
    float mean = s * (1.0f / 128.0f);
    float var = ss * (1.0f / 128.0f) - mean * mean;
    float rstd = rsqrtf(var + 1e-5f);
    float4 gg = ((const float4*)gamma)[lane];
    float4 bv = ((const float4*)beta)[lane];
    float n[4];
    n[0] = (x.x - mean) * rstd * gg.x + bv.x;
    n[1] = (x.y - mean) * rstd * gg.y + bv.y;
    n[2] = (x.z - mean) * rstd * gg.z + bv.z;
    n[3] = (x.w - mean) * rstd * gg.w + bv.w;
    float4 o;
    o.x = tf32f(n[0]); o.y = tf32f(n[1]); o.z = tf32f(n[2]); o.w = tf32f(n[3]);
    ((float4*)(g_z + (size_t)warp * D))[lane] = o;
    float a0 = 0, a1 = 0, a2 = 0, a3 = 0;
    #pragma unroll
    for (int j = 0; j < 4; j++) {
        float4 w = *(const float4*)(bw + (lane * 4 + j) * 4);
        a0 += n[j] * w.x; a1 += n[j] * w.y; a2 += n[j] * w.z; a3 += n[j] * w.w;
    }
    #pragma unroll
    for (int o2 = 16; o2; o2 >>= 1) {
        a0 += __shfl_xor_sync(0xffffffffu, a0, o2);
        a1 += __shfl_xor_sync(0xffffffffu, a1, o2);
        a2 += __shfl_xor_sync(0xffffffffu, a2, o2);
        a3 += __shfl_xor_sync(0xffffffffu, a3, o2);
    }
    if (lane == 0) {
        float* p = g_bias + (size_t)warp * 4;
        p[0] = a0 + bb[0]; p[1] = a1 + bb[1];
        p[2] = a2 + bb[2]; p[3] = a3 + bb[3];
    }
}

// ---------------- fused q/k/v/g projections (128x128, occ 2) -----------------
// grid (4, 2048): x = which weight, y = m-block
__global__ void __launch_bounds__(256, 2) proj_mma(
    const float* __restrict__ qb, const float* __restrict__ kb,
    const float* __restrict__ vb, const float* __restrict__ gb)
{
    extern __shared__ float sp[];
    float (*As)[36] = (float(*)[36])sp;
    float (*Bs)[136] = (float(*)[136])(sp + 3 * 128 * 36);
    int which = blockIdx.x;
    int m0 = blockIdx.y * 128;
    const float* W = which == 0 ? g_wq : which == 1 ? g_wk : which == 2 ? g_wv : g_wg;
    const float* Bv = which == 0 ? qb : which == 1 ? kb : which == 2 ? vb : gb;
    int tid = threadIdx.x, lane = tid & 31, wid = tid >> 5;
    int wr = wid >> 2, wc = wid & 3;
    float acc[4][4][4] = {};
    const float* Abase = g_z + (size_t)m0 * 128;
    const int iters = 4;
    cpa_A32(As, Abase, 128, tid); cpa_B32(Bs, W, 128, tid); cpa_commit();
    cpa_A32(As + 128, Abase + 32, 128, tid);
    cpa_B32(Bs + 32, W + 32 * 128, 128, tid); cpa_commit();
    for (int i = 0; i < iters; i++) {
        cpa_wait<1>();
        __syncthreads();
        comp32(As + (i % 3) * 128, Bs + (i % 3) * 32, acc, wr, wc, lane);
        if (i + 2 < iters) {
            cpa_A32(As + ((i + 2) % 3) * 128, Abase + (i + 2) * 32, 128, tid);
            cpa_B32(Bs + ((i + 2) % 3) * 32, W + (size_t)(i + 2) * 32 * 128, 128, tid);
        }
        cpa_commit();
    }
    __syncthreads();
    int t = lane & 3, g = lane >> 2;
    int b = m0 >> 9;
    int l0 = m0 & 511;
    float (*S)[132] = (float(*)[132])sp;

    if (which != 1) {
        #pragma unroll
        for (int mi = 0; mi < 4; mi++) {
            int r = wr * 64 + mi * 16 + g;
            #pragma unroll
            for (int ni = 0; ni < 4; ni++) {
                int c = wc * 32 + ni * 8 + t * 2;
                float b0 = Bv[c], b1 = Bv[c + 1];
                if (which == 3) {
                    *(float2*)&S[r][c] = make_float2(
                        1.f / (1.f + __expf(-(acc[mi][ni][0] + b0))),
                        1.f / (1.f + __expf(-(acc[mi][ni][1] + b1))));
                    *(float2*)&S[r + 8][c] = make_float2(
                        1.f / (1.f + __expf(-(acc[mi][ni][2] + b0))),
                        1.f / (1.f + __expf(-(acc[mi][ni][3] + b1))));
                } else {
                    *(float2*)&S[r][c] = make_float2(tf32f(acc[mi][ni][0] + b0),
                                                     tf32f(acc[mi][ni][1] + b1));
                    *(float2*)&S[r + 8][c] = make_float2(tf32f(acc[mi][ni][2] + b0),
                                                         tf32f(acc[mi][ni][3] + b1));
                }
            }
        }
        __syncthreads();
        if (which == 3) {
            #pragma unroll
            for (int p = 0; p < 16; p++) {
                int idx = p * 256 + tid;
                int row = idx >> 5, c4 = (idx & 31) * 4;
                *(float4*)(g_sig + (size_t)(m0 + row) * 128 + c4) = *(float4*)&S[row][c4];
            }
        } else {
            float* dst = (which == 0) ? g_qm : g_vt;
            #pragma unroll
            for (int p = 0; p < 16; p++) {
                int idx = p * 256 + tid;
                int row = idx >> 5, c4 = (idx & 31) * 4;
                int hh = c4 >> 5, cc = c4 & 31;
                *(float4*)(dst + ((size_t)hh * 512 + l0 + row) * R_DIM + b * 32 + cc) =
                    *(float4*)&S[row][c4];
            }
        }
    } else {
        #pragma unroll
        for (int mi = 0; mi < 4; mi++) {
            int r = wr * 64 + mi * 16 + g;
            #pragma unroll
            for (int ni = 0; ni < 4; ni++) {
                int c = wc * 32 + ni * 8 + t * 2;
                float b0 = Bv[c], b1 = Bv[c + 1];
                S[c][r] = tf32f(acc[mi][ni][0] + b0);
                S[c + 1][r] = tf32f(acc[mi][ni][1] + b1);
                S[c][r + 8] = tf32f(acc[mi][ni][2] + b0);
                S[c + 1][r + 8] = tf32f(acc[mi][ni][3] + b1);
            }
        }
        __syncthreads();
        #pragma unroll
        for (int p = 0; p < 16; p++) {
            int idx = p * 256 + tid;
            int c = idx >> 5, l4 = (idx & 31) * 4;
            *(float4*)(g_kT + ((size_t)(c >> 5) * R_DIM + b * 32 + (c & 31)) * 512 + l0 + l4) =
                *(float4*)&S[c][l4];
        }
    }
}

// ---------------- logits: 128x256 tiles, split-K=4, 4-stage pipeline ---------
// grid (2, 4, 16): x = k-block (256), y = l-block (128), z = h*4+sk
__global__ void __launch_bounds__(256, 1) att_mma() {
    extern __shared__ float sp[];
    float (*As)[36] = (float(*)[36])sp;                       // 4 x 128
    float (*Bs)[264] = (float(*)[264])(sp + 4 * 128 * 36);    // 4 x 32
    int n0 = blockIdx.x * 256, m0 = blockIdx.y * 128;
    int h = blockIdx.z >> 2, sk = blockIdx.z & 3;
    int tid = threadIdx.x, lane = tid & 31, wid = tid >> 5;
    int wrow = wid >> 2, wcol = wid & 3;
    const float* Aq = g_qm + (size_t)h * L * R_DIM + (size_t)m0 * R_DIM + (size_t)sk * 4096;
    const float* Bk = g_kT + (size_t)h * R_DIM * 512 + (size_t)sk * 4096 * 512 + n0;
    float acc[4][8][4] = {};
    const int iters = 4096 / 32;
    cpa_A32(As, Aq, R_DIM, tid); cpa_B256(Bs, Bk, 512, tid); cpa_commit();
    cpa_A32(As + 128, Aq + 32, R_DIM, tid);
    cpa_B256(Bs + 32, Bk + (size_t)32 * 512, 512, tid); cpa_commit();
    cpa_A32(As + 256, Aq + 64, R_DIM, tid);
    cpa_B256(Bs + 64, Bk + (size_t)64 * 512, 512, tid); cpa_commit();
    for (int i = 0; i < iters; i++) {
        cpa_wait<2>();
        __syncthreads();
        comp_w64(As + (i & 3) * 128, Bs + (i & 3) * 32, acc, wrow, wcol, lane);
        if (i + 3 < iters) {
            cpa_A32(As + ((i + 3) & 3) * 128, Aq + (i + 3) * 32, R_DIM, tid);
            cpa_B256(Bs + ((i + 3) & 3) * 32, Bk + (size_t)(i + 3) * 32 * 512, 512, tid);
        }
        cpa_commit();
    }
    int t = lane & 3, g = lane >> 2;
    float* outp = g_part + (size_t)blockIdx.z * LL;
    #pragma unroll
    for (int mi = 0; mi < 4; mi++) {
        int l = m0 + wrow * 64 + mi * 16 + g;
        #pragma unroll
        for (int ni = 0; ni < 8; ni++) {
            int k = n0 + wcol * 64 + ni * 8 + t * 2;
            *(float2*)(outp + (size_t)l * 512 + k) =
                make_float2(acc[mi][ni][0], acc[mi][ni][1]);
            *(float2*)(outp + (size_t)(l + 8) * 512 + k) =
                make_float2(acc[mi][ni][2], acc[mi][ni][3]);
        }
    }
}

// ---------------- split-K reduce + scale + bias + softmax --------------------
__global__ void softmax2(float scale) {
    __shared__ float red[4];
    int h = blockIdx.x >> 9, l = blockIdx.x & 511;
    int tth = threadIdx.x;
    int warp = tth >> 5, lane = tth & 31;
    int k = tth * 4;
    float4 x = make_float4(0.f, 0.f, 0.f, 0.f);
    #pragma unroll
    for (int sk = 0; sk < 4; sk++) {
        const float4 p = *(const float4*)(g_part +
            ((size_t)(h * 4 + sk) * 512 + l) * 512 + k);
        x.x += p.x; x.y += p.y; x.z += p.z; x.w += p.w;
    }
    const float* bp = g_bias + ((size_t)l * 512 + k) * 4 + h;
    x.x = x.x * scale + bp[0];
    x.y = x.y * scale + bp[4];
    x.z = x.z * scale + bp[8];
    x.w = x.w * scale + bp[12];
    float m = fmaxf(fmaxf(x.x, x.y), fmaxf(x.z, x.w));
    #pragma unroll
    for (int o = 16; o; o >>= 1) m = fmaxf(m, __shfl_xor_sync(0xffffffffu, m, o));
    if (lane == 0) red[warp] = m;
    __syncthreads();
    m = fmaxf(fmaxf(red[0], red[1]), fmaxf(red[2], red[3]));
    __syncthreads();
    x.x = expf(x.x - m); x.y = expf(x.y - m);
    x.z = expf(x.z - m); x.w = expf(x.w - m);
    float s = x.x + x.y + x.z + x.w;
    #pragma unroll
    for (int o = 16; o; o >>= 1) s += __shfl_xor_sync(0xffffffffu, s, o);
    if (lane == 0) red[warp] = s;
    __syncthreads();
    s = red[0] + red[1] + red[2] + red[3];
    float inv = 1.0f / s;
    x.x = tf32f(x.x * inv); x.y = tf32f(x.y * inv);
    x.z = tf32f(x.z * inv); x.w = tf32f(x.w * inv);
    *(float4*)(g_att + ((size_t)(h * 512 + l)) * 512 + k) = x;
}

// ---------------- O = att @ V (128x128, occ 2), fused gating -----------------
// grid (128, 4, 4)
__global__ void __launch_bounds__(256, 2) o_mma() {
    extern __shared__ float sp[];
    float (*As)[36] = (float(*)[36])sp;
    float (*Bs)[136] = (float(*)[136])(sp + 3 * 128 * 36);
    int n0 = blockIdx.x * 128, m0 = blockIdx.y * 128, h = blockIdx.z;
    int tid = threadIdx.x, lane = tid & 31, wid = tid >> 5;
    int wr = wid >> 2, wc = wid & 3;
    const float* Aa = g_att + (size_t)h * LL + (size_t)m0 * 512;
    const float* Bv = g_vt + (size_t)h * L * R_DIM + n0;
    float acc[4][4][4] = {};
    const int iters = 512 / 32;
    cpa_A32(As, Aa, 512, tid); cpa_B32(Bs, Bv, R_DIM, tid); cpa_commit();
    cpa_A32(As + 128, Aa + 32, 512, tid);
    cpa_B32(Bs + 32, Bv + (size_t)32 * R_DIM, R_DIM, tid); cpa_commit();
    for (int i = 0; i < iters; i++) {
        cpa_wait<1>();
        __syncthreads();
        comp32(As + (i % 3) * 128, Bs + (i % 3) * 32, acc, wr, wc, lane);
        if (i + 2 < iters) {
            cpa_A32(As + ((i + 2) % 3) * 128, Aa + (i + 2) * 32, 512, tid);
            cpa_B32(Bs + ((i + 2) % 3) * 32, Bv + (size_t)(i + 2) * 32 * R_DIM, R_DIM, tid);
        }
        cpa_commit();
    }
    int t = lane & 3, g = lane >> 2;
    float* outp = g_o + (size_t)h * L * R_DIM;
    #pragma unroll
    for (int mi = 0; mi < 4; mi++) {
        int l = m0 + wr * 64 + mi * 16 + g;
        #pragma unroll
        for (int ni = 0; ni < 4; ni++) {
            int n = n0 + wc * 32 + ni * 8 + t * 2;
            int bb = n >> 5, cc = n & 31;
            const float* sig0 = g_sig + ((size_t)bb * 512 + l) * 128 + h * 32 + cc;
            float2 s0 = *(const float2*)sig0;
            float2 s1 = *(const float2*)(sig0 + 8 * 128);
            *(float2*)(outp + (size_t)l * R_DIM + n) =
                make_float2(tf32f(acc[mi][ni][0] * s0.x), tf32f(acc[mi][ni][1] * s0.y));
            *(float2*)(outp + (size_t)(l + 8) * R_DIM + n) =
                make_float2(tf32f(acc[mi][ni][2] * s1.x), tf32f(acc[mi][ni][3] * s1.y));
        }
    }
}

// ---------------- final: out = g_o @ ow + ob (pipelined) ---------------------
// grid (2048)
__global__ void __launch_bounds__(256, 2) out_mma(const float* __restrict__ ob,
                                                  float* __restrict__ out) {
    extern __shared__ float sp[];
    float (*As)[36] = (float(*)[36])sp;
    float (*Bs)[136] = (float(*)[136])(sp + 3 * 128 * 36);
    int m0 = blockIdx.x * 128;
    int b = m0 >> 9, l0 = m0 & 511;
    int tid = threadIdx.x, lane = tid & 31, wid = tid >> 5;
    int wr = wid >> 2, wc = wid & 3;
    float acc[4][4][4] = {};
    const int iters = 4;
    #define OUT_APTR(i) (g_o + ((size_t)(i) * 512 + l0) * R_DIM + b * 32)
    cpa_A32(As, OUT_APTR(0), R_DIM, tid);
    cpa_B32(Bs, g_wo, 128, tid); cpa_commit();
    cpa_A32(As + 128, OUT_APTR(1), R_DIM, tid);
    cpa_B32(Bs + 32, g_wo + 32 * 128, 128, tid); cpa_commit();
    for (int i = 0; i < iters; i++) {
        cpa_wait<1>();
        __syncthreads();
        comp32(As + (i % 3) * 128, Bs + (i % 3) * 32, acc, wr, wc, lane);
        if (i + 2 < iters) {
            cpa_A32(As + ((i + 2) % 3) * 128, OUT_APTR(i + 2), R_DIM, tid);
            cpa_B32(Bs + ((i + 2) % 3) * 32, g_wo + (size_t)(i + 2) * 32 * 128, 128, tid);
        }
        cpa_commit();
    }
    #undef OUT_APTR
    int t = lane & 3, g = lane >> 2;
    #pragma unroll
    for (int mi = 0; mi < 4; mi++) {
        int r0 = m0 + wr * 64 + mi * 16 + g;
        #pragma unroll
        for (int ni = 0; ni < 4; ni++) {
            int c = wc * 32 + ni * 8 + t * 2;
            float b0 = ob[c], b1 = ob[c + 1];
            *(float2*)(out + (size_t)r0 * 128 + c) =
                make_float2(acc[mi][ni][0] + b0, acc[mi][ni][1] + b1);
            *(float2*)(out + (size_t)(r0 + 8) * 128 + c) =
                make_float2(acc[mi][ni][2] + b0, acc[mi][ni][3] + b1);
        }
    }
}

// ---------------- launcher ---------------------------------------------------
extern "C" void kernel_launch(void* const* d_in, const int* in_sizes, int n_in,
                              void* d_out, int out_size) {
    const float* z_   = (const float*)d_in[0];
    const float* ln_g = (const float*)d_in[1];
    const float* ln_b = (const float*)d_in[2];
    const float* qw   = (const float*)d_in[3];
    const float* qb   = (const float*)d_in[4];
    const float* kw   = (const float*)d_in[5];
    const float* kb   = (const float*)d_in[6];
    const float* vw   = (const float*)d_in[7];
    const float* vb   = (const float*)d_in[8];
    const float* bw   = (const float*)d_in[9];
    const float* bb   = (const float*)d_in[10];
    const float* gw   = (const float*)d_in[11];
    const float* gb   = (const float*)d_in[12];
    const float* ow   = (const float*)d_in[13];
    const float* ob   = (const float*)d_in[14];
    float* out = (float*)d_out;

    cudaFuncSetAttribute(proj_mma, cudaFuncAttributeMaxDynamicSharedMemorySize, DYN_STD);
    cudaFuncSetAttribute(att_mma, cudaFuncAttributeMaxDynamicSharedMemorySize, DYN_ATT4);
    cudaFuncSetAttribute(o_mma, cudaFuncAttributeMaxDynamicSharedMemorySize, DYN_STD);
    cudaFuncSetAttribute(out_mma, cudaFuncAttributeMaxDynamicSharedMemorySize, DYN_STD);

    round_w<<<(D * D + 255) / 256, 256>>>(qw, kw, vw, gw, ow);
    ln_bias_kernel<<<M_ROWS / 8, 256>>>(z_, ln_g, ln_b, bw, bb);
    proj_mma<<<dim3(4, 2048), 256, DYN_STD>>>(qb, kb, vb, gb);

    float scale = 1.0f / (sqrtf((float)CC) * sqrtf((float)L));
    att_mma<<<dim3(2, 4, 16), 256, DYN_ATT4>>>();
    softmax2<<<NH * L, 128>>>(scale);
    o_mma<<<dim3(128, 4, 4), 256, DYN_STD>>>();
    out_mma<<<2048, 256, DYN_STD>>>(ob, out);
}

// round 15
// speedup vs baseline: 1.5543x; 1.5543x over previous
#include <cuda_runtime.h>
#include <stdint.h>
#include <math.h>

#define L 512
#define D 128
#define NH 4
#define CC 32
#define M_ROWS (L * L)          // 262144
#define R_DIM (L * CC)          // 16384
#define LL (L * L)

// ---------------- scratch ----------------------------------------------------
__device__ float g_z[M_ROWS * D];        // post-LN z (tf32-rounded)
__device__ float g_qm[NH * L * R_DIM];   // q [h][l][bc] tf32 (m-major)
__device__ float g_kT[NH * R_DIM * L];   // k [h][bc][l] tf32 (k-major)
__device__ float g_vt[NH * L * R_DIM];   // v [h][k2][bc] tf32
__device__ float g_sig[M_ROWS * D];      // sigmoid gate
__device__ float g_bias[M_ROWS * NH];    // [(l*512+k), h]
__device__ float g_part[32 * LL];        // [h*8+sk][l][k] split-K partials
__device__ float g_att[NH * LL];         // softmax probs tf32
__device__ float g_o[NH * L * R_DIM];    // gated o tf32
__device__ float g_wq[D * D], g_wk[D * D], g_wv[D * D], g_wg[D * D], g_wo[D * D];

// ---------------- helpers ----------------------------------------------------
__device__ __forceinline__ unsigned tf32c(float x) {
    unsigned u; asm("cvt.rna.tf32.f32 %0, %1;" : "=r"(u) : "f"(x)); return u;
}
__device__ __forceinline__ float tf32f(float x) { return __uint_as_float(tf32c(x)); }

__device__ __forceinline__ void mma8(float* c, const unsigned* a, const unsigned* b) {
    asm volatile(
        "mma.sync.aligned.m16n8k8.row.col.f32.tf32.tf32.f32 "
        "{%0,%1,%2,%3},{%4,%5,%6,%7},{%8,%9},{%0,%1,%2,%3};"
        : "+f"(c[0]), "+f"(c[1]), "+f"(c[2]), "+f"(c[3])
        : "r"(a[0]), "r"(a[1]), "r"(a[2]), "r"(a[3]), "r"(b[0]), "r"(b[1]));
}

__device__ __forceinline__ void cpa16(uint32_t dst, const float* src) {
    asm volatile("cp.async.cg.shared.global [%0], [%1], 16;\n" :: "r"(dst), "l"(src));
}
__device__ __forceinline__ void cpa_commit() { asm volatile("cp.async.commit_group;\n"); }
template <int N> __device__ __forceinline__ void cpa_wait() {
    asm volatile("cp.async.wait_group %0;\n" :: "n"(N));
}
__device__ __forceinline__ uint32_t sa(const void* p) {
    return (uint32_t)__cvta_generic_to_shared(p);
}

// ---- tile loaders ----
__device__ __forceinline__ void cpa_A32(float (*S)[36], const float* src, size_t ld, int tid) {
    #pragma unroll
    for (int p = 0; p < 4; p++) {
        int idx = p * 256 + tid;
        int row = idx >> 3, c4 = (idx & 7) * 4;
        cpa16(sa(&S[row][c4]), src + (size_t)row * ld + c4);
    }
}
__device__ __forceinline__ void cpa_B32(float (*S)[136], const float* src, size_t ld, int tid) {
    #pragma unroll
    for (int p = 0; p < 4; p++) {
        int idx = p * 256 + tid;
        int r = idx >> 5, c4 = (idx & 31) * 4;
        cpa16(sa(&S[r][c4]), src + (size_t)r * ld + c4);
    }
}
__device__ __forceinline__ void cpa_B256(float (*S)[264], const float* src, size_t ld, int tid) {
    #pragma unroll
    for (int p = 0; p < 8; p++) {
        int idx = p * 256 + tid;
        int r = idx >> 6, c4 = (idx & 63) * 4;
        cpa16(sa(&S[r][c4]), src + (size_t)r * ld + c4);
    }
}

// ---- compute: 64x32 warp tile ----
__device__ __forceinline__ void comp32(const float (*Am)[36], const float (*Bs)[136],
                                       float acc[4][4][4], int wr, int wc, int lane) {
    int t = lane & 3, g = lane >> 2;
    #pragma unroll
    for (int ks = 0; ks < 32; ks += 8) {
        unsigned a[4][4], b[4][2];
        #pragma unroll
        for (int mi = 0; mi < 4; mi++) {
            int r = wr * 64 + mi * 16 + g;
            a[mi][0] = __float_as_uint(Am[r][ks + t]);
            a[mi][1] = __float_as_uint(Am[r + 8][ks + t]);
            a[mi][2] = __float_as_uint(Am[r][ks + t + 4]);
            a[mi][3] = __float_as_uint(Am[r + 8][ks + t + 4]);
        }
        #pragma unroll
        for (int ni = 0; ni < 4; ni++) {
            int c = wc * 32 + ni * 8 + g;
            b[ni][0] = __float_as_uint(Bs[ks + t][c]);
            b[ni][1] = __float_as_uint(Bs[ks + t + 4][c]);
        }
        #pragma unroll
        for (int mi = 0; mi < 4; mi++)
            #pragma unroll
            for (int ni = 0; ni < 4; ni++) mma8(acc[mi][ni], a[mi], b[ni]);
    }
}

// ---- compute: 64x64 warp tile ----
__device__ __forceinline__ void comp_w64(const float (*Am)[36], const float (*Bs)[264],
                                         float acc[4][8][4], int wrow, int wcol, int lane) {
    int t = lane & 3, g = lane >> 2;
    #pragma unroll
    for (int ks = 0; ks < 32; ks += 8) {
        unsigned a[4][4], b[8][2];
        #pragma unroll
        for (int mi = 0; mi < 4; mi++) {
            int r = wrow * 64 + mi * 16 + g;
            a[mi][0] = __float_as_uint(Am[r][ks + t]);
            a[mi][1] = __float_as_uint(Am[r + 8][ks + t]);
            a[mi][2] = __float_as_uint(Am[r][ks + t + 4]);
            a[mi][3] = __float_as_uint(Am[r + 8][ks + t + 4]);
        }
        #pragma unroll
        for (int ni = 0; ni < 8; ni++) {
            int c = wcol * 64 + ni * 8 + g;
            b[ni][0] = __float_as_uint(Bs[ks + t][c]);
            b[ni][1] = __float_as_uint(Bs[ks + t + 4][c]);
        }
        #pragma unroll
        for (int mi = 0; mi < 4; mi++)
            #pragma unroll
            for (int ni = 0; ni < 8; ni++) mma8(acc[mi][ni], a[mi], b[ni]);
    }
}

#define DYN_STD ((3 * 128 * 36 + 3 * 32 * 136) * 4)   // 107520
#define DYN_ATT ((3 * 128 * 36 + 3 * 32 * 264) * 4)   // 156672

// ---------------- small kernels ----------------------------------------------
__global__ void round_w(const float* __restrict__ qw, const float* __restrict__ kw,
                        const float* __restrict__ vw, const float* __restrict__ gw,
                        const float* __restrict__ ow) {
    int i = blockIdx.x * 256 + threadIdx.x;
    if (i >= D * D) return;
    g_wq[i] = tf32f(qw[i]); g_wk[i] = tf32f(kw[i]);
    g_wv[i] = tf32f(vw[i]); g_wg[i] = tf32f(gw[i]);
    g_wo[i] = tf32f(ow[i]);
}

// fused LN (writes tf32 g_z) + bias projection, one pass over z_
__global__ void ln_bias_kernel(const float* __restrict__ zin,
                               const float* __restrict__ gamma,
                               const float* __restrict__ beta,
                               const float* __restrict__ bw,
                               const float* __restrict__ bb) {
    int warp = (blockIdx.x * blockDim.x + threadIdx.x) >> 5;
    int lane = threadIdx.x & 31;
    if (warp >= M_ROWS) return;
    float4 x = ((const float4*)(zin + (size_t)warp * D))[lane];
    float s = x.x + x.y + x.z + x.w;
    float ss = x.x * x.x + x.y * x.y + x.z * x.z + x.w * x.w;
    #pragma unroll
    for (int o = 16; o; o >>= 1) {
        s += __shfl_xor_sync(0xffffffffu, s, o);
        ss += __shfl_xor_sync(0xffffffffu, ss, o);
    }
    float mean = s * (1.0f / 128.0f);
    float var = ss * (1.0f / 128.0f) - mean * mean;
    float rstd = rsqrtf(var + 1e-5f);
    float4 gg = ((const float4*)gamma)[lane];
    float4 bv = ((const float4*)beta)[lane];
    float n[4];
    n[0] = (x.x - mean) * rstd * gg.x + bv.x;
    n[1] = (x.y - mean) * rstd * gg.y + bv.y;
    n[2] = (x.z - mean) * rstd * gg.z + bv.z;
    n[3] = (x.w - mean) * rstd * gg.w + bv.w;
    float4 o;
    o.x = tf32f(n[0]); o.y = tf32f(n[1]); o.z = tf32f(n[2]); o.w = tf32f(n[3]);
    ((float4*)(g_z + (size_t)warp * D))[lane] = o;
    float a0 = 0, a1 = 0, a2 = 0, a3 = 0;
    #pragma unroll
    for (int j = 0; j < 4; j++) {
        float4 w = *(const float4*)(bw + (lane * 4 + j) * 4);
        a0 += n[j] * w.x; a1 += n[j] * w.y; a2 += n[j] * w.z; a3 += n[j] * w.w;
    }
    #pragma unroll
    for (int o2 = 16; o2; o2 >>= 1) {
        a0 += __shfl_xor_sync(0xffffffffu, a0, o2);
        a1 += __shfl_xor_sync(0xffffffffu, a1, o2);
        a2 += __shfl_xor_sync(0xffffffffu, a2, o2);
        a3 += __shfl_xor_sync(0xffffffffu, a3, o2);
    }
    if (lane == 0) {
        float* p = g_bias + (size_t)warp * 4;
        p[0] = a0 + bb[0]; p[1] = a1 + bb[1];
        p[2] = a2 + bb[2]; p[3] = a3 + bb[3];
    }
}

// ---------------- fused q/k/v/g projections (128x128, occ 2) -----------------
// grid (4, 2048): x = which weight, y = m-block
__global__ void __launch_bounds__(256, 2) proj_mma(
    const float* __restrict__ qb, const float* __restrict__ kb,
    const float* __restrict__ vb, const float* __restrict__ gb)
{
    extern __shared__ float sp[];
    float (*As)[36] = (float(*)[36])sp;
    float (*Bs)[136] = (float(*)[136])(sp + 3 * 128 * 36);
    int which = blockIdx.x;
    int m0 = blockIdx.y * 128;
    const float* W = which == 0 ? g_wq : which == 1 ? g_wk : which == 2 ? g_wv : g_wg;
    const float* Bv = which == 0 ? qb : which == 1 ? kb : which == 2 ? vb : gb;
    int tid = threadIdx.x, lane = tid & 31, wid = tid >> 5;
    int wr = wid >> 2, wc = wid & 3;
    float acc[4][4][4] = {};
    const float* Abase = g_z + (size_t)m0 * 128;
    const int iters = 4;
    cpa_A32(As, Abase, 128, tid); cpa_B32(Bs, W, 128, tid); cpa_commit();
    cpa_A32(As + 128, Abase + 32, 128, tid);
    cpa_B32(Bs + 32, W + 32 * 128, 128, tid); cpa_commit();
    for (int i = 0; i < iters; i++) {
        cpa_wait<1>();
        __syncthreads();
        comp32(As + (i % 3) * 128, Bs + (i % 3) * 32, acc, wr, wc, lane);
        if (i + 2 < iters) {
            cpa_A32(As + ((i + 2) % 3) * 128, Abase + (i + 2) * 32, 128, tid);
            cpa_B32(Bs + ((i + 2) % 3) * 32, W + (size_t)(i + 2) * 32 * 128, 128, tid);
        }
        cpa_commit();
    }
    __syncthreads();
    int t = lane & 3, g = lane >> 2;
    int b = m0 >> 9;
    int l0 = m0 & 511;
    float (*S)[132] = (float(*)[132])sp;

    if (which != 1) {
        #pragma unroll
        for (int mi = 0; mi < 4; mi++) {
            int r = wr * 64 + mi * 16 + g;
            #pragma unroll
            for (int ni = 0; ni < 4; ni++) {
                int c = wc * 32 + ni * 8 + t * 2;
                float b0 = Bv[c], b1 = Bv[c + 1];
                if (which == 3) {
                    *(float2*)&S[r][c] = make_float2(
                        1.f / (1.f + __expf(-(acc[mi][ni][0] + b0))),
                        1.f / (1.f + __expf(-(acc[mi][ni][1] + b1))));
                    *(float2*)&S[r + 8][c] = make_float2(
                        1.f / (1.f + __expf(-(acc[mi][ni][2] + b0))),
                        1.f / (1.f + __expf(-(acc[mi][ni][3] + b1))));
                } else {
                    *(float2*)&S[r][c] = make_float2(tf32f(acc[mi][ni][0] + b0),
                                                     tf32f(acc[mi][ni][1] + b1));
                    *(float2*)&S[r + 8][c] = make_float2(tf32f(acc[mi][ni][2] + b0),
                                                         tf32f(acc[mi][ni][3] + b1));
                }
            }
        }
        __syncthreads();
        if (which == 3) {
            #pragma unroll
            for (int p = 0; p < 16; p++) {
                int idx = p * 256 + tid;
                int row = idx >> 5, c4 = (idx & 31) * 4;
                *(float4*)(g_sig + (size_t)(m0 + row) * 128 + c4) = *(float4*)&S[row][c4];
            }
        } else {
            float* dst = (which == 0) ? g_qm : g_vt;
            #pragma unroll
            for (int p = 0; p < 16; p++) {
                int idx = p * 256 + tid;
                int row = idx >> 5, c4 = (idx & 31) * 4;
                int hh = c4 >> 5, cc = c4 & 31;
                *(float4*)(dst + ((size_t)hh * 512 + l0 + row) * R_DIM + b * 32 + cc) =
                    *(float4*)&S[row][c4];
            }
        }
    } else {
        #pragma unroll
        for (int mi = 0; mi < 4; mi++) {
            int r = wr * 64 + mi * 16 + g;
            #pragma unroll
            for (int ni = 0; ni < 4; ni++) {
                int c = wc * 32 + ni * 8 + t * 2;
                float b0 = Bv[c], b1 = Bv[c + 1];
                S[c][r] = tf32f(acc[mi][ni][0] + b0);
                S[c + 1][r] = tf32f(acc[mi][ni][1] + b1);
                S[c][r + 8] = tf32f(acc[mi][ni][2] + b0);
                S[c + 1][r + 8] = tf32f(acc[mi][ni][3] + b1);
            }
        }
        __syncthreads();
        #pragma unroll
        for (int p = 0; p < 16; p++) {
            int idx = p * 256 + tid;
            int c = idx >> 5, l4 = (idx & 31) * 4;
            *(float4*)(g_kT + ((size_t)(c >> 5) * R_DIM + b * 32 + (c & 31)) * 512 + l0 + l4) =
                *(float4*)&S[c][l4];
        }
    }
}

// ---------------- logits: 128x256 tiles, split-K=8 ---------------------------
// grid (2, 4, 32)
__global__ void __launch_bounds__(256, 1) att_mma() {
    extern __shared__ float sp[];
    float (*As)[36] = (float(*)[36])sp;
    float (*Bs)[264] = (float(*)[264])(sp + 3 * 128 * 36);
    int n0 = blockIdx.x * 256, m0 = blockIdx.y * 128;
    int h = blockIdx.z >> 3, sk = blockIdx.z & 7;
    int tid = threadIdx.x, lane = tid & 31, wid = tid >> 5;
    int wrow = wid >> 2, wcol = wid & 3;
    const float* Aq = g_qm + (size_t)h * L * R_DIM + (size_t)m0 * R_DIM + (size_t)sk * 2048;
    const float* Bk = g_kT + (size_t)h * R_DIM * 512 + (size_t)sk * 2048 * 512 + n0;
    float acc[4][8][4] = {};
    const int iters = 2048 / 32;
    cpa_A32(As, Aq, R_DIM, tid); cpa_B256(Bs, Bk, 512, tid); cpa_commit();
    cpa_A32(As + 128, Aq + 32, R_DIM, tid);
    cpa_B256(Bs + 32, Bk + (size_t)32 * 512, 512, tid); cpa_commit();
    for (int i = 0; i < iters; i++) {
        cpa_wait<1>();
        __syncthreads();
        comp_w64(As + (i % 3) * 128, Bs + (i % 3) * 32, acc, wrow, wcol, lane);
        if (i + 2 < iters) {
            cpa_A32(As + ((i + 2) % 3) * 128, Aq + (i + 2) * 32, R_DIM, tid);
            cpa_B256(Bs + ((i + 2) % 3) * 32, Bk + (size_t)(i + 2) * 32 * 512, 512, tid);
        }
        cpa_commit();
    }
    int t = lane & 3, g = lane >> 2;
    float* outp = g_part + (size_t)blockIdx.z * LL;
    #pragma unroll
    for (int mi = 0; mi < 4; mi++) {
        int l = m0 + wrow * 64 + mi * 16 + g;
        #pragma unroll
        for (int ni = 0; ni < 8; ni++) {
            int k = n0 + wcol * 64 + ni * 8 + t * 2;
            *(float2*)(outp + (size_t)l * 512 + k) =
                make_float2(acc[mi][ni][0], acc[mi][ni][1]);
            *(float2*)(outp + (size_t)(l + 8) * 512 + k) =
                make_float2(acc[mi][ni][2], acc[mi][ni][3]);
        }
    }
}

// ---------------- split-K reduce + scale + bias + softmax --------------------
__global__ void softmax2(float scale) {
    __shared__ float red[4];
    int h = blockIdx.x >> 9, l = blockIdx.x & 511;
    int tth = threadIdx.x;
    int warp = tth >> 5, lane = tth & 31;
    int k = tth * 4;
    float4 x = make_float4(0.f, 0.f, 0.f, 0.f);
    #pragma unroll
    for (int sk = 0; sk < 8; sk++) {
        const float4 p = *(const float4*)(g_part +
            ((size_t)(h * 8 + sk) * 512 + l) * 512 + k);
        x.x += p.x; x.y += p.y; x.z += p.z; x.w += p.w;
    }
    const float* bp = g_bias + ((size_t)l * 512 + k) * 4 + h;
    x.x = x.x * scale + bp[0];
    x.y = x.y * scale + bp[4];
    x.z = x.z * scale + bp[8];
    x.w = x.w * scale + bp[12];
    float m = fmaxf(fmaxf(x.x, x.y), fmaxf(x.z, x.w));
    #pragma unroll
    for (int o = 16; o; o >>= 1) m = fmaxf(m, __shfl_xor_sync(0xffffffffu, m, o));
    if (lane == 0) red[warp] = m;
    __syncthreads();
    m = fmaxf(fmaxf(red[0], red[1]), fmaxf(red[2], red[3]));
    __syncthreads();
    x.x = __expf(x.x - m); x.y = __expf(x.y - m);
    x.z = __expf(x.z - m); x.w = __expf(x.w - m);
    float s = x.x + x.y + x.z + x.w;
    #pragma unroll
    for (int o = 16; o; o >>= 1) s += __shfl_xor_sync(0xffffffffu, s, o);
    if (lane == 0) red[warp] = s;
    __syncthreads();
    s = red[0] + red[1] + red[2] + red[3];
    float inv = 1.0f / s;
    x.x = tf32f(x.x * inv); x.y = tf32f(x.y * inv);
    x.z = tf32f(x.z * inv); x.w = tf32f(x.w * inv);
    *(float4*)(g_att + ((size_t)(h * 512 + l)) * 512 + k) = x;
}

// ---------------- O = att @ V (128x128, occ 2), fused gating -----------------
// grid (128, 4, 4)
__global__ void __launch_bounds__(256, 2) o_mma() {
    extern __shared__ float sp[];
    float (*As)[36] = (float(*)[36])sp;
    float (*Bs)[136] = (float(*)[136])(sp + 3 * 128 * 36);
    int n0 = blockIdx.x * 128, m0 = blockIdx.y * 128, h = blockIdx.z;
    int tid = threadIdx.x, lane = tid & 31, wid = tid >> 5;
    int wr = wid >> 2, wc = wid & 3;
    const float* Aa = g_att + (size_t)h * LL + (size_t)m0 * 512;
    const float* Bv = g_vt + (size_t)h * L * R_DIM + n0;
    float acc[4][4][4] = {};
    const int iters = 512 / 32;
    cpa_A32(As, Aa, 512, tid); cpa_B32(Bs, Bv, R_DIM, tid); cpa_commit();
    cpa_A32(As + 128, Aa + 32, 512, tid);
    cpa_B32(Bs + 32, Bv + (size_t)32 * R_DIM, R_DIM, tid); cpa_commit();
    for (int i = 0; i < iters; i++) {
        cpa_wait<1>();
        __syncthreads();
        comp32(As + (i % 3) * 128, Bs + (i % 3) * 32, acc, wr, wc, lane);
        if (i + 2 < iters) {
            cpa_A32(As + ((i + 2) % 3) * 128, Aa + (i + 2) * 32, 512, tid);
            cpa_B32(Bs + ((i + 2) % 3) * 32, Bv + (size_t)(i + 2) * 32 * R_DIM, R_DIM, tid);
        }
        cpa_commit();
    }
    int t = lane & 3, g = lane >> 2;
    float* outp = g_o + (size_t)h * L * R_DIM;
    #pragma unroll
    for (int mi = 0; mi < 4; mi++) {
        int l = m0 + wr * 64 + mi * 16 + g;
        #pragma unroll
        for (int ni = 0; ni < 4; ni++) {
            int n = n0 + wc * 32 + ni * 8 + t * 2;
            int bb = n >> 5, cc = n & 31;
            const float* sig0 = g_sig + ((size_t)bb * 512 + l) * 128 + h * 32 + cc;
            float2 s0 = *(const float2*)sig0;
            float2 s1 = *(const float2*)(sig0 + 8 * 128);
            *(float2*)(outp + (size_t)l * R_DIM + n) =
                make_float2(tf32f(acc[mi][ni][0] * s0.x), tf32f(acc[mi][ni][1] * s0.y));
            *(float2*)(outp + (size_t)(l + 8) * R_DIM + n) =
                make_float2(tf32f(acc[mi][ni][2] * s1.x), tf32f(acc[mi][ni][3] * s1.y));
        }
    }
}

// ---------------- final: out = g_o @ ow + ob (pipelined) ---------------------
// grid (2048)
__global__ void __launch_bounds__(256, 2) out_mma(const float* __restrict__ ob,
                                                  float* __restrict__ out) {
    extern __shared__ float sp[];
    float (*As)[36] = (float(*)[36])sp;
    float (*Bs)[136] = (float(*)[136])(sp + 3 * 128 * 36);
    int m0 = blockIdx.x * 128;
    int b = m0 >> 9, l0 = m0 & 511;
    int tid = threadIdx.x, lane = tid & 31, wid = tid >> 5;
    int wr = wid >> 2, wc = wid & 3;
    float acc[4][4][4] = {};
    const int iters = 4;
    #define OUT_APTR(i) (g_o + ((size_t)(i) * 512 + l0) * R_DIM + b * 32)
    cpa_A32(As, OUT_APTR(0), R_DIM, tid);
    cpa_B32(Bs, g_wo, 128, tid); cpa_commit();
    cpa_A32(As + 128, OUT_APTR(1), R_DIM, tid);
    cpa_B32(Bs + 32, g_wo + 32 * 128, 128, tid); cpa_commit();
    for (int i = 0; i < iters; i++) {
        cpa_wait<1>();
        __syncthreads();
        comp32(As + (i % 3) * 128, Bs + (i % 3) * 32, acc, wr, wc, lane);
        if (i + 2 < iters) {
            cpa_A32(As + ((i + 2) % 3) * 128, OUT_APTR(i + 2), R_DIM, tid);
            cpa_B32(Bs + ((i + 2) % 3) * 32, g_wo + (size_t)(i + 2) * 32 * 128, 128, tid);
        }
        cpa_commit();
    }
    #undef OUT_APTR
    int t = lane & 3, g = lane >> 2;
    #pragma unroll
    for (int mi = 0; mi < 4; mi++) {
        int r0 = m0 + wr * 64 + mi * 16 + g;
        #pragma unroll
        for (int ni = 0; ni < 4; ni++) {
            int c = wc * 32 + ni * 8 + t * 2;
            float b0 = ob[c], b1 = ob[c + 1];
            *(float2*)(out + (size_t)r0 * 128 + c) =
                make_float2(acc[mi][ni][0] + b0, acc[mi][ni][1] + b1);
            *(float2*)(out + (size_t)(r0 + 8) * 128 + c) =
                make_float2(acc[mi][ni][2] + b0, acc[mi][ni][3] + b1);
        }
    }
}

// ---------------- launcher ---------------------------------------------------
extern "C" void kernel_launch(void* const* d_in, const int* in_sizes, int n_in,
                              void* d_out, int out_size) {
    const float* z_   = (const float*)d_in[0];
    const float* ln_g = (const float*)d_in[1];
    const float* ln_b = (const float*)d_in[2];
    const float* qw   = (const float*)d_in[3];
    const float* qb   = (const float*)d_in[4];
    const float* kw   = (const float*)d_in[5];
    const float* kb   = (const float*)d_in[6];
    const float* vw   = (const float*)d_in[7];
    const float* vb   = (const float*)d_in[8];
    const float* bw   = (const float*)d_in[9];
    const float* bb   = (const float*)d_in[10];
    const float* gw   = (const float*)d_in[11];
    const float* gb   = (const float*)d_in[12];
    const float* ow   = (const float*)d_in[13];
    const float* ob   = (const float*)d_in[14];
    float* out = (float*)d_out;

    cudaFuncSetAttribute(proj_mma, cudaFuncAttributeMaxDynamicSharedMemorySize, DYN_STD);
    cudaFuncSetAttribute(att_mma, cudaFuncAttributeMaxDynamicSharedMemorySize, DYN_ATT);
    cudaFuncSetAttribute(o_mma, cudaFuncAttributeMaxDynamicSharedMemorySize, DYN_STD);
    cudaFuncSetAttribute(out_mma, cudaFuncAttributeMaxDynamicSharedMemorySize, DYN_STD);

    round_w<<<(D * D + 255) / 256, 256>>>(qw, kw, vw, gw, ow);
    ln_bias_kernel<<<M_ROWS / 8, 256>>>(z_, ln_g, ln_b, bw, bb);
    proj_mma<<<dim3(4, 2048), 256, DYN_STD>>>(qb, kb, vb, gb);

    float scale = 1.0f / (sqrtf((float)CC) * sqrtf((float)L));
    att_mma<<<dim3(2, 4, 32), 256, DYN_ATT>>>();
    softmax2<<<NH * L, 128>>>(scale);
    o_mma<<<dim3(128, 4, 4), 256, DYN_STD>>>();
    out_mma<<<2048, 256, DYN_STD>>>(ob, out);
}

// round 16
// speedup vs baseline: 1.5569x; 1.0017x over previous
#include <cuda_runtime.h>
#include <stdint.h>
#include <math.h>

#define L 512
#define D 128
#define NH 4
#define CC 32
#define M_ROWS (L * L)          // 262144
#define R_DIM (L * CC)          // 16384
#define LL (L * L)

// ---------------- scratch ----------------------------------------------------
__device__ float g_z[M_ROWS * D];        // post-LN z (tf32-rounded)
__device__ float g_qm[NH * L * R_DIM];   // q [h][l][bc] tf32 (m-major)
__device__ float g_kT[NH * R_DIM * L];   // k [h][bc][l] tf32 (k-major)
__device__ float g_vt[NH * L * R_DIM];   // v [h][k2][bc] tf32
__device__ float g_sig[M_ROWS * D];      // sigmoid gate
__device__ float g_bias[M_ROWS * NH];    // [(l*512+k), h]
__device__ float g_part[32 * LL];        // [h*8+sk][l][k] split-K partials
__device__ float g_att[NH * LL];         // softmax probs tf32
__device__ float g_o[NH * L * R_DIM];    // gated o tf32
__device__ float g_wq[D * D], g_wk[D * D], g_wv[D * D], g_wg[D * D], g_wo[D * D];

// ---------------- helpers ----------------------------------------------------
__device__ __forceinline__ unsigned tf32c(float x) {
    unsigned u; asm("cvt.rna.tf32.f32 %0, %1;" : "=r"(u) : "f"(x)); return u;
}
__device__ __forceinline__ float tf32f(float x) { return __uint_as_float(tf32c(x)); }

__device__ __forceinline__ void mma8(float* c, const unsigned* a, const unsigned* b) {
    asm volatile(
        "mma.sync.aligned.m16n8k8.row.col.f32.tf32.tf32.f32 "
        "{%0,%1,%2,%3},{%4,%5,%6,%7},{%8,%9},{%0,%1,%2,%3};"
        : "+f"(c[0]), "+f"(c[1]), "+f"(c[2]), "+f"(c[3])
        : "r"(a[0]), "r"(a[1]), "r"(a[2]), "r"(a[3]), "r"(b[0]), "r"(b[1]));
}

__device__ __forceinline__ void cpa16(uint32_t dst, const float* src) {
    asm volatile("cp.async.cg.shared.global [%0], [%1], 16;\n" :: "r"(dst), "l"(src));
}
__device__ __forceinline__ void cpa_commit() { asm volatile("cp.async.commit_group;\n"); }
template <int N> __device__ __forceinline__ void cpa_wait() {
    asm volatile("cp.async.wait_group %0;\n" :: "n"(N));
}
__device__ __forceinline__ uint32_t sa(const void* p) {
    return (uint32_t)__cvta_generic_to_shared(p);
}

// ---- tile loaders ----
__device__ __forceinline__ void cpa_A32(float (*S)[36], const float* src, size_t ld, int tid) {
    #pragma unroll
    for (int p = 0; p < 4; p++) {
        int idx = p * 256 + tid;
        int row = idx >> 3, c4 = (idx & 7) * 4;
        cpa16(sa(&S[row][c4]), src + (size_t)row * ld + c4);
    }
}
__device__ __forceinline__ void cpa_B32(float (*S)[136], const float* src, size_t ld, int tid) {
    #pragma unroll
    for (int p = 0; p < 4; p++) {
        int idx = p * 256 + tid;
        int r = idx >> 5, c4 = (idx & 31) * 4;
        cpa16(sa(&S[r][c4]), src + (size_t)r * ld + c4);
    }
}
__device__ __forceinline__ void cpa_B256(float (*S)[264], const float* src, size_t ld, int tid) {
    #pragma unroll
    for (int p = 0; p < 8; p++) {
        int idx = p * 256 + tid;
        int r = idx >> 6, c4 = (idx & 63) * 4;
        cpa16(sa(&S[r][c4]), src + (size_t)r * ld + c4);
    }
}

// ---- compute: 64x32 warp tile ----
__device__ __forceinline__ void comp32(const float (*Am)[36], const float (*Bs)[136],
                                       float acc[4][4][4], int wr, int wc, int lane) {
    int t = lane & 3, g = lane >> 2;
    #pragma unroll
    for (int ks = 0; ks < 32; ks += 8) {
        unsigned a[4][4], b[4][2];
        #pragma unroll
        for (int mi = 0; mi < 4; mi++) {
            int r = wr * 64 + mi * 16 + g;
            a[mi][0] = __float_as_uint(Am[r][ks + t]);
            a[mi][1] = __float_as_uint(Am[r + 8][ks + t]);
            a[mi][2] = __float_as_uint(Am[r][ks + t + 4]);
            a[mi][3] = __float_as_uint(Am[r + 8][ks + t + 4]);
        }
        #pragma unroll
        for (int ni = 0; ni < 4; ni++) {
            int c = wc * 32 + ni * 8 + g;
            b[ni][0] = __float_as_uint(Bs[ks + t][c]);
            b[ni][1] = __float_as_uint(Bs[ks + t + 4][c]);
        }
        #pragma unroll
        for (int mi = 0; mi < 4; mi++)
            #pragma unroll
            for (int ni = 0; ni < 4; ni++) mma8(acc[mi][ni], a[mi], b[ni]);
    }
}

// ---- compute: 64x64 warp tile ----
__device__ __forceinline__ void comp_w64(const float (*Am)[36], const float (*Bs)[264],
                                         float acc[4][8][4], int wrow, int wcol, int lane) {
    int t = lane & 3, g = lane >> 2;
    #pragma unroll
    for (int ks = 0; ks < 32; ks += 8) {
        unsigned a[4][4], b[8][2];
        #pragma unroll
        for (int mi = 0; mi < 4; mi++) {
            int r = wrow * 64 + mi * 16 + g;
            a[mi][0] = __float_as_uint(Am[r][ks + t]);
            a[mi][1] = __float_as_uint(Am[r + 8][ks + t]);
            a[mi][2] = __float_as_uint(Am[r][ks + t + 4]);
            a[mi][3] = __float_as_uint(Am[r + 8][ks + t + 4]);
        }
        #pragma unroll
        for (int ni = 0; ni < 8; ni++) {
            int c = wcol * 64 + ni * 8 + g;
            b[ni][0] = __float_as_uint(Bs[ks + t][c]);
            b[ni][1] = __float_as_uint(Bs[ks + t + 4][c]);
        }
        #pragma unroll
        for (int mi = 0; mi < 4; mi++)
            #pragma unroll
            for (int ni = 0; ni < 8; ni++) mma8(acc[mi][ni], a[mi], b[ni]);
    }
}

#define DYN_STD ((3 * 128 * 36 + 3 * 32 * 136) * 4)   // 107520
#define DYN_ATT ((3 * 128 * 36 + 3 * 32 * 264) * 4)   // 156672

// ---------------- small kernels ----------------------------------------------
__global__ void round_w(const float* __restrict__ qw, const float* __restrict__ kw,
                        const float* __restrict__ vw, const float* __restrict__ gw,
                        const float* __restrict__ ow) {
    int i = blockIdx.x * 256 + threadIdx.x;
    if (i >= D * D) return;
    g_wq[i] = tf32f(qw[i]); g_wk[i] = tf32f(kw[i]);
    g_wv[i] = tf32f(vw[i]); g_wg[i] = tf32f(gw[i]);
    g_wo[i] = tf32f(ow[i]);
}

// fused LN (writes tf32 g_z) + bias projection, one pass over z_
__global__ void ln_bias_kernel(const float* __restrict__ zin,
                               const float* __restrict__ gamma,
                               const float* __restrict__ beta,
                               const float* __restrict__ bw,
                               const float* __restrict__ bb) {
    int warp = (blockIdx.x * blockDim.x + threadIdx.x) >> 5;
    int lane = threadIdx.x & 31;
    if (warp >= M_ROWS) return;
    float4 x = ((const float4*)(zin + (size_t)warp * D))[lane];
    float s = x.x + x.y + x.z + x.w;
    float ss = x.x * x.x + x.y * x.y + x.z * x.z + x.w * x.w;
    #pragma unroll
    for (int o = 16; o; o >>= 1) {
        s += __shfl_xor_sync(0xffffffffu, s, o);
        ss += __shfl_xor_sync(0xffffffffu, ss, o);
    }
    float mean = s * (1.0f / 128.0f);
    float var = ss * (1.0f / 128.0f) - mean * mean;
    float rstd = rsqrtf(var + 1e-5f);
    float4 gg = ((const float4*)gamma)[lane];
    float4 bv = ((const float4*)beta)[lane];
    float n[4];
    n[0] = (x.x - mean) * rstd * gg.x + bv.x;
    n[1] = (x.y - mean) * rstd * gg.y + bv.y;
    n[2] = (x.z - mean) * rstd * gg.z + bv.z;
    n[3] = (x.w - mean) * rstd * gg.w + bv.w;
    float4 o;
    o.x = tf32f(n[0]); o.y = tf32f(n[1]); o.z = tf32f(n[2]); o.w = tf32f(n[3]);
    ((float4*)(g_z + (size_t)warp * D))[lane] = o;
    float a0 = 0, a1 = 0, a2 = 0, a3 = 0;
    #pragma unroll
    for (int j = 0; j < 4; j++) {
        float4 w = *(const float4*)(bw + (lane * 4 + j) * 4);
        a0 += n[j] * w.x; a1 += n[j] * w.y; a2 += n[j] * w.z; a3 += n[j] * w.w;
    }
    #pragma unroll
    for (int o2 = 16; o2; o2 >>= 1) {
        a0 += __shfl_xor_sync(0xffffffffu, a0, o2);
        a1 += __shfl_xor_sync(0xffffffffu, a1, o2);
        a2 += __shfl_xor_sync(0xffffffffu, a2, o2);
        a3 += __shfl_xor_sync(0xffffffffu, a3, o2);
    }
    if (lane == 0) {
        float* p = g_bias + (size_t)warp * 4;
        p[0] = a0 + bb[0]; p[1] = a1 + bb[1];
        p[2] = a2 + bb[2]; p[3] = a3 + bb[3];
    }
}

// ---------------- fused q/k/v/g projections (128x128, occ 2) -----------------
// grid (4, 2048): x = which weight, y = m-block
__global__ void __launch_bounds__(256, 2) proj_mma(
    const float* __restrict__ qb, const float* __restrict__ kb,
    const float* __restrict__ vb, const float* __restrict__ gb)
{
    extern __shared__ float sp[];
    float (*As)[36] = (float(*)[36])sp;
    float (*Bs)[136] = (float(*)[136])(sp + 3 * 128 * 36);
    int which = blockIdx.x;
    int m0 = blockIdx.y * 128;
    const float* W = which == 0 ? g_wq : which == 1 ? g_wk : which == 2 ? g_wv : g_wg;
    const float* Bv = which == 0 ? qb : which == 1 ? kb : which == 2 ? vb : gb;
    int tid = threadIdx.x, lane = tid & 31, wid = tid >> 5;
    int wr = wid >> 2, wc = wid & 3;
    float acc[4][4][4] = {};
    const float* Abase = g_z + (size_t)m0 * 128;
    const int iters = 4;
    cpa_A32(As, Abase, 128, tid); cpa_B32(Bs, W, 128, tid); cpa_commit();
    cpa_A32(As + 128, Abase + 32, 128, tid);
    cpa_B32(Bs + 32, W + 32 * 128, 128, tid); cpa_commit();
    for (int i = 0; i < iters; i++) {
        cpa_wait<1>();
        __syncthreads();
        comp32(As + (i % 3) * 128, Bs + (i % 3) * 32, acc, wr, wc, lane);
        if (i + 2 < iters) {
            cpa_A32(As + ((i + 2) % 3) * 128, Abase + (i + 2) * 32, 128, tid);
            cpa_B32(Bs + ((i + 2) % 3) * 32, W + (size_t)(i + 2) * 32 * 128, 128, tid);
        }
        cpa_commit();
    }
    __syncthreads();
    int t = lane & 3, g = lane >> 2;
    int b = m0 >> 9;
    int l0 = m0 & 511;
    float (*S)[132] = (float(*)[132])sp;

    if (which != 1) {
        #pragma unroll
        for (int mi = 0; mi < 4; mi++) {
            int r = wr * 64 + mi * 16 + g;
            #pragma unroll
            for (int ni = 0; ni < 4; ni++) {
                int c = wc * 32 + ni * 8 + t * 2;
                float b0 = Bv[c], b1 = Bv[c + 1];
                if (which == 3) {
                    *(float2*)&S[r][c] = make_float2(
                        1.f / (1.f + __expf(-(acc[mi][ni][0] + b0))),
                        1.f / (1.f + __expf(-(acc[mi][ni][1] + b1))));
                    *(float2*)&S[r + 8][c] = make_float2(
                        1.f / (1.f + __expf(-(acc[mi][ni][2] + b0))),
                        1.f / (1.f + __expf(-(acc[mi][ni][3] + b1))));
                } else {
                    *(float2*)&S[r][c] = make_float2(tf32f(acc[mi][ni][0] + b0),
                                                     tf32f(acc[mi][ni][1] + b1));
                    *(float2*)&S[r + 8][c] = make_float2(tf32f(acc[mi][ni][2] + b0),
                                                         tf32f(acc[mi][ni][3] + b1));
                }
            }
        }
        __syncthreads();
        if (which == 3) {
            #pragma unroll
            for (int p = 0; p < 16; p++) {
                int idx = p * 256 + tid;
                int row = idx >> 5, c4 = (idx & 31) * 4;
                *(float4*)(g_sig + (size_t)(m0 + row) * 128 + c4) = *(float4*)&S[row][c4];
            }
        } else {
            float* dst = (which == 0) ? g_qm : g_vt;
            #pragma unroll
            for (int p = 0; p < 16; p++) {
                int idx = p * 256 + tid;
                int row = idx >> 5, c4 = (idx & 31) * 4;
                int hh = c4 >> 5, cc = c4 & 31;
                *(float4*)(dst + ((size_t)hh * 512 + l0 + row) * R_DIM + b * 32 + cc) =
                    *(float4*)&S[row][c4];
            }
        }
    } else {
        #pragma unroll
        for (int mi = 0; mi < 4; mi++) {
            int r = wr * 64 + mi * 16 + g;
            #pragma unroll
            for (int ni = 0; ni < 4; ni++) {
                int c = wc * 32 + ni * 8 + t * 2;
                float b0 = Bv[c], b1 = Bv[c + 1];
                S[c][r] = tf32f(acc[mi][ni][0] + b0);
                S[c + 1][r] = tf32f(acc[mi][ni][1] + b1);
                S[c][r + 8] = tf32f(acc[mi][ni][2] + b0);
                S[c + 1][r + 8] = tf32f(acc[mi][ni][3] + b1);
            }
        }
        __syncthreads();
        #pragma unroll
        for (int p = 0; p < 16; p++) {
            int idx = p * 256 + tid;
            int c = idx >> 5, l4 = (idx & 31) * 4;
            *(float4*)(g_kT + ((size_t)(c >> 5) * R_DIM + b * 32 + (c & 31)) * 512 + l0 + l4) =
                *(float4*)&S[c][l4];
        }
    }
}

// ---------------- logits: 128x256 tiles, split-K=8 ---------------------------
// grid (2, 4, 32)
__global__ void __launch_bounds__(256, 1) att_mma() {
    extern __shared__ float sp[];
    float (*As)[36] = (float(*)[36])sp;
    float (*Bs)[264] = (float(*)[264])(sp + 3 * 128 * 36);
    int n0 = blockIdx.x * 256, m0 = blockIdx.y * 128;
    int h = blockIdx.z >> 3, sk = blockIdx.z & 7;
    int tid = threadIdx.x, lane = tid & 31, wid = tid >> 5;
    int wrow = wid >> 2, wcol = wid & 3;
    const float* Aq = g_qm + (size_t)h * L * R_DIM + (size_t)m0 * R_DIM + (size_t)sk * 2048;
    const float* Bk = g_kT + (size_t)h * R_DIM * 512 + (size_t)sk * 2048 * 512 + n0;
    float acc[4][8][4] = {};
    const int iters = 2048 / 32;
    cpa_A32(As, Aq, R_DIM, tid); cpa_B256(Bs, Bk, 512, tid); cpa_commit();
    cpa_A32(As + 128, Aq + 32, R_DIM, tid);
    cpa_B256(Bs + 32, Bk + (size_t)32 * 512, 512, tid); cpa_commit();
    for (int i = 0; i < iters; i++) {
        cpa_wait<1>();
        __syncthreads();
        comp_w64(As + (i % 3) * 128, Bs + (i % 3) * 32, acc, wrow, wcol, lane);
        if (i + 2 < iters) {
            cpa_A32(As + ((i + 2) % 3) * 128, Aq + (i + 2) * 32, R_DIM, tid);
            cpa_B256(Bs + ((i + 2) % 3) * 32, Bk + (size_t)(i + 2) * 32 * 512, 512, tid);
        }
        cpa_commit();
    }
    int t = lane & 3, g = lane >> 2;
    float* outp = g_part + (size_t)blockIdx.z * LL;
    #pragma unroll
    for (int mi = 0; mi < 4; mi++) {
        int l = m0 + wrow * 64 + mi * 16 + g;
        #pragma unroll
        for (int ni = 0; ni < 8; ni++) {
            int k = n0 + wcol * 64 + ni * 8 + t * 2;
            *(float2*)(outp + (size_t)l * 512 + k) =
                make_float2(acc[mi][ni][0], acc[mi][ni][1]);
            *(float2*)(outp + (size_t)(l + 8) * 512 + k) =
                make_float2(acc[mi][ni][2], acc[mi][ni][3]);
        }
    }
}

// ---------------- split-K reduce + scale + bias + softmax --------------------
__global__ void softmax2(float scale) {
    __shared__ float red[4];
    int h = blockIdx.x >> 9, l = blockIdx.x & 511;
    int tth = threadIdx.x;
    int warp = tth >> 5, lane = tth & 31;
    int k = tth * 4;
    float4 x = make_float4(0.f, 0.f, 0.f, 0.f);
    #pragma unroll
    for (int sk = 0; sk < 8; sk++) {
        const float4 p = *(const float4*)(g_part +
            ((size_t)(h * 8 + sk) * 512 + l) * 512 + k);
        x.x += p.x; x.y += p.y; x.z += p.z; x.w += p.w;
    }
    const float* bp = g_bias + ((size_t)l * 512 + k) * 4 + h;
    x.x = x.x * scale + bp[0];
    x.y = x.y * scale + bp[4];
    x.z = x.z * scale + bp[8];
    x.w = x.w * scale + bp[12];
    float m = fmaxf(fmaxf(x.x, x.y), fmaxf(x.z, x.w));
    #pragma unroll
    for (int o = 16; o; o >>= 1) m = fmaxf(m, __shfl_xor_sync(0xffffffffu, m, o));
    if (lane == 0) red[warp] = m;
    __syncthreads();
    m = fmaxf(fmaxf(red[0], red[1]), fmaxf(red[2], red[3]));
    __syncthreads();
    x.x = __expf(x.x - m); x.y = __expf(x.y - m);
    x.z = __expf(x.z - m); x.w = __expf(x.w - m);
    float s = x.x + x.y + x.z + x.w;
    #pragma unroll
    for (int o = 16; o; o >>= 1) s += __shfl_xor_sync(0xffffffffu, s, o);
    if (lane == 0) red[warp] = s;
    __syncthreads();
    s = red[0] + red[1] + red[2] + red[3];
    float inv = 1.0f / s;
    x.x = tf32f(x.x * inv); x.y = tf32f(x.y * inv);
    x.z = tf32f(x.z * inv); x.w = tf32f(x.w * inv);
    *(float4*)(g_att + ((size_t)(h * 512 + l)) * 512 + k) = x;
}

// ---------------- O = att @ V (128x128, occ 2), fused gating -----------------
// grid (4, 128, 4): x = l-block (FAST — co-resident l-blocks share V in L2),
//                   y = bc-block, z = head
__global__ void __launch_bounds__(256, 2) o_mma() {
    extern __shared__ float sp[];
    float (*As)[36] = (float(*)[36])sp;
    float (*Bs)[136] = (float(*)[136])(sp + 3 * 128 * 36);
    int m0 = blockIdx.x * 128, n0 = blockIdx.y * 128, h = blockIdx.z;
    int tid = threadIdx.x, lane = tid & 31, wid = tid >> 5;
    int wr = wid >> 2, wc = wid & 3;
    const float* Aa = g_att + (size_t)h * LL + (size_t)m0 * 512;
    const float* Bv = g_vt + (size_t)h * L * R_DIM + n0;
    float acc[4][4][4] = {};
    const int iters = 512 / 32;
    cpa_A32(As, Aa, 512, tid); cpa_B32(Bs, Bv, R_DIM, tid); cpa_commit();
    cpa_A32(As + 128, Aa + 32, 512, tid);
    cpa_B32(Bs + 32, Bv + (size_t)32 * R_DIM, R_DIM, tid); cpa_commit();
    for (int i = 0; i < iters; i++) {
        cpa_wait<1>();
        __syncthreads();
        comp32(As + (i % 3) * 128, Bs + (i % 3) * 32, acc, wr, wc, lane);
        if (i + 2 < iters) {
            cpa_A32(As + ((i + 2) % 3) * 128, Aa + (i + 2) * 32, 512, tid);
            cpa_B32(Bs + ((i + 2) % 3) * 32, Bv + (size_t)(i + 2) * 32 * R_DIM, R_DIM, tid);
        }
        cpa_commit();
    }
    int t = lane & 3, g = lane >> 2;
    float* outp = g_o + (size_t)h * L * R_DIM;
    #pragma unroll
    for (int mi = 0; mi < 4; mi++) {
        int l = m0 + wr * 64 + mi * 16 + g;
        #pragma unroll
        for (int ni = 0; ni < 4; ni++) {
            int n = n0 + wc * 32 + ni * 8 + t * 2;
            int bb = n >> 5, cc = n & 31;
            const float* sig0 = g_sig + ((size_t)bb * 512 + l) * 128 + h * 32 + cc;
            float2 s0 = *(const float2*)sig0;
            float2 s1 = *(const float2*)(sig0 + 8 * 128);
            *(float2*)(outp + (size_t)l * R_DIM + n) =
                make_float2(tf32f(acc[mi][ni][0] * s0.x), tf32f(acc[mi][ni][1] * s0.y));
            *(float2*)(outp + (size_t)(l + 8) * R_DIM + n) =
                make_float2(tf32f(acc[mi][ni][2] * s1.x), tf32f(acc[mi][ni][3] * s1.y));
        }
    }
}

// ---------------- final: out = g_o @ ow + ob (pipelined) ---------------------
// grid (2048)
__global__ void __launch_bounds__(256, 2) out_mma(const float* __restrict__ ob,
                                                  float* __restrict__ out) {
    extern __shared__ float sp[];
    float (*As)[36] = (float(*)[36])sp;
    float (*Bs)[136] = (float(*)[136])(sp + 3 * 128 * 36);
    int m0 = blockIdx.x * 128;
    int b = m0 >> 9, l0 = m0 & 511;
    int tid = threadIdx.x, lane = tid & 31, wid = tid >> 5;
    int wr = wid >> 2, wc = wid & 3;
    float acc[4][4][4] = {};
    const int iters = 4;
    #define OUT_APTR(i) (g_o + ((size_t)(i) * 512 + l0) * R_DIM + b * 32)
    cpa_A32(As, OUT_APTR(0), R_DIM, tid);
    cpa_B32(Bs, g_wo, 128, tid); cpa_commit();
    cpa_A32(As + 128, OUT_APTR(1), R_DIM, tid);
    cpa_B32(Bs + 32, g_wo + 32 * 128, 128, tid); cpa_commit();
    for (int i = 0; i < iters; i++) {
        cpa_wait<1>();
        __syncthreads();
        comp32(As + (i % 3) * 128, Bs + (i % 3) * 32, acc, wr, wc, lane);
        if (i + 2 < iters) {
            cpa_A32(As + ((i + 2) % 3) * 128, OUT_APTR(i + 2), R_DIM, tid);
            cpa_B32(Bs + ((i + 2) % 3) * 32, g_wo + (size_t)(i + 2) * 32 * 128, 128, tid);
        }
        cpa_commit();
    }
    #undef OUT_APTR
    int t = lane & 3, g = lane >> 2;
    #pragma unroll
    for (int mi = 0; mi < 4; mi++) {
        int r0 = m0 + wr * 64 + mi * 16 + g;
        #pragma unroll
        for (int ni = 0; ni < 4; ni++) {
            int c = wc * 32 + ni * 8 + t * 2;
            float b0 = ob[c], b1 = ob[c + 1];
            *(float2*)(out + (size_t)r0 * 128 + c) =
                make_float2(acc[mi][ni][0] + b0, acc[mi][ni][1] + b1);
            *(float2*)(out + (size_t)(r0 + 8) * 128 + c) =
                make_float2(acc[mi][ni][2] + b0, acc[mi][ni][3] + b1);
        }
    }
}

// ---------------- launcher ---------------------------------------------------
extern "C" void kernel_launch(void* const* d_in, const int* in_sizes, int n_in,
                              void* d_out, int out_size) {
    const float* z_   = (const float*)d_in[0];
    const float* ln_g = (const float*)d_in[1];
    const float* ln_b = (const float*)d_in[2];
    const float* qw   = (const float*)d_in[3];
    const float* qb   = (const float*)d_in[4];
    const float* kw   = (const float*)d_in[5];
    const float* kb   = (const float*)d_in[6];
    const float* vw   = (const float*)d_in[7];
    const float* vb   = (const float*)d_in[8];
    const float* bw   = (const float*)d_in[9];
    const float* bb   = (const float*)d_in[10];
    const float* gw   = (const float*)d_in[11];
    const float* gb   = (const float*)d_in[12];
    const float* ow   = (const float*)d_in[13];
    const float* ob   = (const float*)d_in[14];
    float* out = (float*)d_out;

    cudaFuncSetAttribute(proj_mma, cudaFuncAttributeMaxDynamicSharedMemorySize, DYN_STD);
    cudaFuncSetAttribute(att_mma, cudaFuncAttributeMaxDynamicSharedMemorySize, DYN_ATT);
    cudaFuncSetAttribute(o_mma, cudaFuncAttributeMaxDynamicSharedMemorySize, DYN_STD);
    cudaFuncSetAttribute(out_mma, cudaFuncAttributeMaxDynamicSharedMemorySize, DYN_STD);

    round_w<<<(D * D + 255) / 256, 256>>>(qw, kw, vw, gw, ow);
    ln_bias_kernel<<<M_ROWS / 8, 256>>>(z_, ln_g, ln_b, bw, bb);
    proj_mma<<<dim3(4, 2048), 256, DYN_STD>>>(qb, kb, vb, gb);

    float scale = 1.0f / (sqrtf((float)CC) * sqrtf((float)L));
    att_mma<<<dim3(2, 4, 32), 256, DYN_ATT>>>();
    softmax2<<<NH * L, 128>>>(scale);
    o_mma<<<dim3(4, 128, 4), 256, DYN_STD>>>();
    out_mma<<<2048, 256, DYN_STD>>>(ob, out);
}

// round 17
// speedup vs baseline: 1.5605x; 1.0023x over previous
#include <cuda_runtime.h>
#include <stdint.h>
#include <math.h>

#define L 512
#define D 128
#define NH 4
#define CC 32
#define M_ROWS (L * L)          // 262144
#define R_DIM (L * CC)          // 16384
#define LL (L * L)

// ---------------- scratch ----------------------------------------------------
__device__ float g_z[M_ROWS * D];        // post-LN z (tf32-rounded)
__device__ float g_qm[NH * L * R_DIM];   // q [h][l][bc] tf32 (m-major)
__device__ float g_kT[NH * R_DIM * L];   // k [h][bc][l] tf32 (k-major)
__device__ float g_vt[NH * L * R_DIM];   // v [h][k2][bc] tf32
__device__ float g_sig[M_ROWS * D];      // sigmoid gate
__device__ float g_bias[M_ROWS * NH];    // [(l*512+k), h]
__device__ float g_part[32 * LL];        // [h*8+sk][l][k] split-K partials
__device__ float g_att[NH * LL];         // softmax probs tf32
__device__ float g_o[NH * L * R_DIM];    // gated o tf32
__device__ float g_wq[D * D], g_wk[D * D], g_wv[D * D], g_wg[D * D], g_wo[D * D];

// ---------------- helpers ----------------------------------------------------
__device__ __forceinline__ unsigned tf32c(float x) {
    unsigned u; asm("cvt.rna.tf32.f32 %0, %1;" : "=r"(u) : "f"(x)); return u;
}
__device__ __forceinline__ float tf32f(float x) { return __uint_as_float(tf32c(x)); }

__device__ __forceinline__ void mma8(float* c, const unsigned* a, const unsigned* b) {
    asm volatile(
        "mma.sync.aligned.m16n8k8.row.col.f32.tf32.tf32.f32 "
        "{%0,%1,%2,%3},{%4,%5,%6,%7},{%8,%9},{%0,%1,%2,%3};"
        : "+f"(c[0]), "+f"(c[1]), "+f"(c[2]), "+f"(c[3])
        : "r"(a[0]), "r"(a[1]), "r"(a[2]), "r"(a[3]), "r"(b[0]), "r"(b[1]));
}

__device__ __forceinline__ void cpa16(uint32_t dst, const float* src) {
    asm volatile("cp.async.cg.shared.global [%0], [%1], 16;\n" :: "r"(dst), "l"(src));
}
__device__ __forceinline__ void cpa_commit() { asm volatile("cp.async.commit_group;\n"); }
template <int N> __device__ __forceinline__ void cpa_wait() {
    asm volatile("cp.async.wait_group %0;\n" :: "n"(N));
}
__device__ __forceinline__ uint32_t sa(const void* p) {
    return (uint32_t)__cvta_generic_to_shared(p);
}

// ---- tile loaders ----
__device__ __forceinline__ void cpa_A32(float (*S)[36], const float* src, size_t ld, int tid) {
    #pragma unroll
    for (int p = 0; p < 4; p++) {
        int idx = p * 256 + tid;
        int row = idx >> 3, c4 = (idx & 7) * 4;
        cpa16(sa(&S[row][c4]), src + (size_t)row * ld + c4);
    }
}
__device__ __forceinline__ void cpa_B32(float (*S)[136], const float* src, size_t ld, int tid) {
    #pragma unroll
    for (int p = 0; p < 4; p++) {
        int idx = p * 256 + tid;
        int r = idx >> 5, c4 = (idx & 31) * 4;
        cpa16(sa(&S[r][c4]), src + (size_t)r * ld + c4);
    }
}
__device__ __forceinline__ void cpa_B256(float (*S)[264], const float* src, size_t ld, int tid) {
    #pragma unroll
    for (int p = 0; p < 8; p++) {
        int idx = p * 256 + tid;
        int r = idx >> 6, c4 = (idx & 63) * 4;
        cpa16(sa(&S[r][c4]), src + (size_t)r * ld + c4);
    }
}

// ---- compute: 64x32 warp tile ----
__device__ __forceinline__ void comp32(const float (*Am)[36], const float (*Bs)[136],
                                       float acc[4][4][4], int wr, int wc, int lane) {
    int t = lane & 3, g = lane >> 2;
    #pragma unroll
    for (int ks = 0; ks < 32; ks += 8) {
        unsigned a[4][4], b[4][2];
        #pragma unroll
        for (int mi = 0; mi < 4; mi++) {
            int r = wr * 64 + mi * 16 + g;
            a[mi][0] = __float_as_uint(Am[r][ks + t]);
            a[mi][1] = __float_as_uint(Am[r + 8][ks + t]);
            a[mi][2] = __float_as_uint(Am[r][ks + t + 4]);
            a[mi][3] = __float_as_uint(Am[r + 8][ks + t + 4]);
        }
        #pragma unroll
        for (int ni = 0; ni < 4; ni++) {
            int c = wc * 32 + ni * 8 + g;
            b[ni][0] = __float_as_uint(Bs[ks + t][c]);
            b[ni][1] = __float_as_uint(Bs[ks + t + 4][c]);
        }
        #pragma unroll
        for (int mi = 0; mi < 4; mi++)
            #pragma unroll
            for (int ni = 0; ni < 4; ni++) mma8(acc[mi][ni], a[mi], b[ni]);
    }
}

// ---- compute: 64x64 warp tile ----
__device__ __forceinline__ void comp_w64(const float (*Am)[36], const float (*Bs)[264],
                                         float acc[4][8][4], int wrow, int wcol, int lane) {
    int t = lane & 3, g = lane >> 2;
    #pragma unroll
    for (int ks = 0; ks < 32; ks += 8) {
        unsigned a[4][4], b[8][2];
        #pragma unroll
        for (int mi = 0; mi < 4; mi++) {
            int r = wrow * 64 + mi * 16 + g;
            a[mi][0] = __float_as_uint(Am[r][ks + t]);
            a[mi][1] = __float_as_uint(Am[r + 8][ks + t]);
            a[mi][2] = __float_as_uint(Am[r][ks + t + 4]);
            a[mi][3] = __float_as_uint(Am[r + 8][ks + t + 4]);
        }
        #pragma unroll
        for (int ni = 0; ni < 8; ni++) {
            int c = wcol * 64 + ni * 8 + g;
            b[ni][0] = __float_as_uint(Bs[ks + t][c]);
            b[ni][1] = __float_as_uint(Bs[ks + t + 4][c]);
        }
        #pragma unroll
        for (int mi = 0; mi < 4; mi++)
            #pragma unroll
            for (int ni = 0; ni < 8; ni++) mma8(acc[mi][ni], a[mi], b[ni]);
    }
}

#define DYN_STD ((3 * 128 * 36 + 3 * 32 * 136) * 4)   // 107520
#define DYN_ATT ((3 * 128 * 36 + 3 * 32 * 264) * 4)   // 156672

// ---------------- small kernels ----------------------------------------------
__global__ void round_w(const float* __restrict__ qw, const float* __restrict__ kw,
                        const float* __restrict__ vw, const float* __restrict__ gw,
                        const float* __restrict__ ow) {
    int i = blockIdx.x * 256 + threadIdx.x;
    if (i >= D * D) return;
    g_wq[i] = tf32f(qw[i]); g_wk[i] = tf32f(kw[i]);
    g_wv[i] = tf32f(vw[i]); g_wg[i] = tf32f(gw[i]);
    g_wo[i] = tf32f(ow[i]);
}

// fused LN (writes tf32 g_z) + bias projection, one pass over z_
__global__ void ln_bias_kernel(const float* __restrict__ zin,
                               const float* __restrict__ gamma,
                               const float* __restrict__ beta,
                               const float* __restrict__ bw,
                               const float* __restrict__ bb) {
    int warp = (blockIdx.x * blockDim.x + threadIdx.x) >> 5;
    int lane = threadIdx.x & 31;
    if (warp >= M_ROWS) return;
    float4 x = ((const float4*)(zin + (size_t)warp * D))[lane];
    float s = x.x + x.y + x.z + x.w;
    float ss = x.x * x.x + x.y * x.y + x.z * x.z + x.w * x.w;
    #pragma unroll
    for (int o = 16; o; o >>= 1) {
        s += __shfl_xor_sync(0xffffffffu, s, o);
        ss += __shfl_xor_sync(0xffffffffu, ss, o);
    }
    float mean = s * (1.0f / 128.0f);
    float var = ss * (1.0f / 128.0f) - mean * mean;
    float rstd = rsqrtf(var + 1e-5f);
    float4 gg = ((const float4*)gamma)[lane];
    float4 bv = ((const float4*)beta)[lane];
    float n[4];
    n[0] = (x.x - mean) * rstd * gg.x + bv.x;
    n[1] = (x.y - mean) * rstd * gg.y + bv.y;
    n[2] = (x.z - mean) * rstd * gg.z + bv.z;
    n[3] = (x.w - mean) * rstd * gg.w + bv.w;
    float4 o;
    o.x = tf32f(n[0]); o.y = tf32f(n[1]); o.z = tf32f(n[2]); o.w = tf32f(n[3]);
    ((float4*)(g_z + (size_t)warp * D))[lane] = o;
    float a0 = 0, a1 = 0, a2 = 0, a3 = 0;
    #pragma unroll
    for (int j = 0; j < 4; j++) {
        float4 w = *(const float4*)(bw + (lane * 4 + j) * 4);
        a0 += n[j] * w.x; a1 += n[j] * w.y; a2 += n[j] * w.z; a3 += n[j] * w.w;
    }
    #pragma unroll
    for (int o2 = 16; o2; o2 >>= 1) {
        a0 += __shfl_xor_sync(0xffffffffu, a0, o2);
        a1 += __shfl_xor_sync(0xffffffffu, a1, o2);
        a2 += __shfl_xor_sync(0xffffffffu, a2, o2);
        a3 += __shfl_xor_sync(0xffffffffu, a3, o2);
    }
    if (lane == 0) {
        float* p = g_bias + (size_t)warp * 4;
        p[0] = a0 + bb[0]; p[1] = a1 + bb[1];
        p[2] = a2 + bb[2]; p[3] = a3 + bb[3];
    }
}

// ---------------- q/k/v/g projections (128x128, occ 2) -----------------------
// grid (2, 2048): which = which_base + blockIdx.x  (0=q,1=k,2=v,3=g)
__global__ void __launch_bounds__(256, 2) proj_mma(
    int which_base,
    const float* __restrict__ qb, const float* __restrict__ kb,
    const float* __restrict__ vb, const float* __restrict__ gb)
{
    extern __shared__ float sp[];
    float (*As)[36] = (float(*)[36])sp;
    float (*Bs)[136] = (float(*)[136])(sp + 3 * 128 * 36);
    int which = which_base + blockIdx.x;
    int m0 = blockIdx.y * 128;
    const float* W = which == 0 ? g_wq : which == 1 ? g_wk : which == 2 ? g_wv : g_wg;
    const float* Bv = which == 0 ? qb : which == 1 ? kb : which == 2 ? vb : gb;
    int tid = threadIdx.x, lane = tid & 31, wid = tid >> 5;
    int wr = wid >> 2, wc = wid & 3;
    float acc[4][4][4] = {};
    const float* Abase = g_z + (size_t)m0 * 128;
    const int iters = 4;
    cpa_A32(As, Abase, 128, tid); cpa_B32(Bs, W, 128, tid); cpa_commit();
    cpa_A32(As + 128, Abase + 32, 128, tid);
    cpa_B32(Bs + 32, W + 32 * 128, 128, tid); cpa_commit();
    for (int i = 0; i < iters; i++) {
        cpa_wait<1>();
        __syncthreads();
        comp32(As + (i % 3) * 128, Bs + (i % 3) * 32, acc, wr, wc, lane);
        if (i + 2 < iters) {
            cpa_A32(As + ((i + 2) % 3) * 128, Abase + (i + 2) * 32, 128, tid);
            cpa_B32(Bs + ((i + 2) % 3) * 32, W + (size_t)(i + 2) * 32 * 128, 128, tid);
        }
        cpa_commit();
    }
    __syncthreads();
    int t = lane & 3, g = lane >> 2;
    int b = m0 >> 9;
    int l0 = m0 & 511;
    float (*S)[132] = (float(*)[132])sp;

    if (which != 1) {
        #pragma unroll
        for (int mi = 0; mi < 4; mi++) {
            int r = wr * 64 + mi * 16 + g;
            #pragma unroll
            for (int ni = 0; ni < 4; ni++) {
                int c = wc * 32 + ni * 8 + t * 2;
                float b0 = Bv[c], b1 = Bv[c + 1];
                if (which == 3) {
                    *(float2*)&S[r][c] = make_float2(
                        1.f / (1.f + __expf(-(acc[mi][ni][0] + b0))),
                        1.f / (1.f + __expf(-(acc[mi][ni][1] + b1))));
                    *(float2*)&S[r + 8][c] = make_float2(
                        1.f / (1.f + __expf(-(acc[mi][ni][2] + b0))),
                        1.f / (1.f + __expf(-(acc[mi][ni][3] + b1))));
                } else {
                    *(float2*)&S[r][c] = make_float2(tf32f(acc[mi][ni][0] + b0),
                                                     tf32f(acc[mi][ni][1] + b1));
                    *(float2*)&S[r + 8][c] = make_float2(tf32f(acc[mi][ni][2] + b0),
                                                         tf32f(acc[mi][ni][3] + b1));
                }
            }
        }
        __syncthreads();
        if (which == 3) {
            #pragma unroll
            for (int p = 0; p < 16; p++) {
                int idx = p * 256 + tid;
                int row = idx >> 5, c4 = (idx & 31) * 4;
                *(float4*)(g_sig + (size_t)(m0 + row) * 128 + c4) = *(float4*)&S[row][c4];
            }
        } else {
            float* dst = (which == 0) ? g_qm : g_vt;
            #pragma unroll
            for (int p = 0; p < 16; p++) {
                int idx = p * 256 + tid;
                int row = idx >> 5, c4 = (idx & 31) * 4;
                int hh = c4 >> 5, cc = c4 & 31;
                *(float4*)(dst + ((size_t)hh * 512 + l0 + row) * R_DIM + b * 32 + cc) =
                    *(float4*)&S[row][c4];
            }
        }
    } else {
        #pragma unroll
        for (int mi = 0; mi < 4; mi++) {
            int r = wr * 64 + mi * 16 + g;
            #pragma unroll
            for (int ni = 0; ni < 4; ni++) {
                int c = wc * 32 + ni * 8 + t * 2;
                float b0 = Bv[c], b1 = Bv[c + 1];
                S[c][r] = tf32f(acc[mi][ni][0] + b0);
                S[c + 1][r] = tf32f(acc[mi][ni][1] + b1);
                S[c][r + 8] = tf32f(acc[mi][ni][2] + b0);
                S[c + 1][r + 8] = tf32f(acc[mi][ni][3] + b1);
            }
        }
        __syncthreads();
        #pragma unroll
        for (int p = 0; p < 16; p++) {
            int idx = p * 256 + tid;
            int c = idx >> 5, l4 = (idx & 31) * 4;
            *(float4*)(g_kT + ((size_t)(c >> 5) * R_DIM + b * 32 + (c & 31)) * 512 + l0 + l4) =
                *(float4*)&S[c][l4];
        }
    }
}

// ---------------- logits: 128x256 tiles, split-K=8 ---------------------------
// grid (2, 4, 32)
__global__ void __launch_bounds__(256, 1) att_mma() {
    extern __shared__ float sp[];
    float (*As)[36] = (float(*)[36])sp;
    float (*Bs)[264] = (float(*)[264])(sp + 3 * 128 * 36);
    int n0 = blockIdx.x * 256, m0 = blockIdx.y * 128;
    int h = blockIdx.z >> 3, sk = blockIdx.z & 7;
    int tid = threadIdx.x, lane = tid & 31, wid = tid >> 5;
    int wrow = wid >> 2, wcol = wid & 3;
    const float* Aq = g_qm + (size_t)h * L * R_DIM + (size_t)m0 * R_DIM + (size_t)sk * 2048;
    const float* Bk = g_kT + (size_t)h * R_DIM * 512 + (size_t)sk * 2048 * 512 + n0;
    float acc[4][8][4] = {};
    const int iters = 2048 / 32;
    cpa_A32(As, Aq, R_DIM, tid); cpa_B256(Bs, Bk, 512, tid); cpa_commit();
    cpa_A32(As + 128, Aq + 32, R_DIM, tid);
    cpa_B256(Bs + 32, Bk + (size_t)32 * 512, 512, tid); cpa_commit();
    for (int i = 0; i < iters; i++) {
        cpa_wait<1>();
        __syncthreads();
        comp_w64(As + (i % 3) * 128, Bs + (i % 3) * 32, acc, wrow, wcol, lane);
        if (i + 2 < iters) {
            cpa_A32(As + ((i + 2) % 3) * 128, Aq + (i + 2) * 32, R_DIM, tid);
            cpa_B256(Bs + ((i + 2) % 3) * 32, Bk + (size_t)(i + 2) * 32 * 512, 512, tid);
        }
        cpa_commit();
    }
    int t = lane & 3, g = lane >> 2;
    float* outp = g_part + (size_t)blockIdx.z * LL;
    #pragma unroll
    for (int mi = 0; mi < 4; mi++) {
        int l = m0 + wrow * 64 + mi * 16 + g;
        #pragma unroll
        for (int ni = 0; ni < 8; ni++) {
            int k = n0 + wcol * 64 + ni * 8 + t * 2;
            *(float2*)(outp + (size_t)l * 512 + k) =
                make_float2(acc[mi][ni][0], acc[mi][ni][1]);
            *(float2*)(outp + (size_t)(l + 8) * 512 + k) =
                make_float2(acc[mi][ni][2], acc[mi][ni][3]);
        }
    }
}

// ---------------- split-K reduce + scale + bias + softmax --------------------
__global__ void softmax2(float scale) {
    __shared__ float red[4];
    int h = blockIdx.x >> 9, l = blockIdx.x & 511;
    int tth = threadIdx.x;
    int warp = tth >> 5, lane = tth & 31;
    int k = tth * 4;
    float4 x = make_float4(0.f, 0.f, 0.f, 0.f);
    #pragma unroll
    for (int sk = 0; sk < 8; sk++) {
        const float4 p = *(const float4*)(g_part +
            ((size_t)(h * 8 + sk) * 512 + l) * 512 + k);
        x.x += p.x; x.y += p.y; x.z += p.z; x.w += p.w;
    }
    const float* bp = g_bias + ((size_t)l * 512 + k) * 4 + h;
    x.x = x.x * scale + bp[0];
    x.y = x.y * scale + bp[4];
    x.z = x.z * scale + bp[8];
    x.w = x.w * scale + bp[12];
    float m = fmaxf(fmaxf(x.x, x.y), fmaxf(x.z, x.w));
    #pragma unroll
    for (int o = 16; o; o >>= 1) m = fmaxf(m, __shfl_xor_sync(0xffffffffu, m, o));
    if (lane == 0) red[warp] = m;
    __syncthreads();
    m = fmaxf(fmaxf(red[0], red[1]), fmaxf(red[2], red[3]));
    __syncthreads();
    x.x = __expf(x.x - m); x.y = __expf(x.y - m);
    x.z = __expf(x.z - m); x.w = __expf(x.w - m);
    float s = x.x + x.y + x.z + x.w;
    #pragma unroll
    for (int o = 16; o; o >>= 1) s += __shfl_xor_sync(0xffffffffu, s, o);
    if (lane == 0) red[warp] = s;
    __syncthreads();
    s = red[0] + red[1] + red[2] + red[3];
    float inv = 1.0f / s;
    x.x = tf32f(x.x * inv); x.y = tf32f(x.y * inv);
    x.z = tf32f(x.z * inv); x.w = tf32f(x.w * inv);
    *(float4*)(g_att + ((size_t)(h * 512 + l)) * 512 + k) = x;
}

// ---------------- O = att @ V (128x128, occ 2), fused gating -----------------
// grid (4, 128, 4)
__global__ void __launch_bounds__(256, 2) o_mma() {
    extern __shared__ float sp[];
    float (*As)[36] = (float(*)[36])sp;
    float (*Bs)[136] = (float(*)[136])(sp + 3 * 128 * 36);
    int m0 = blockIdx.x * 128, n0 = blockIdx.y * 128, h = blockIdx.z;
    int tid = threadIdx.x, lane = tid & 31, wid = tid >> 5;
    int wr = wid >> 2, wc = wid & 3;
    const float* Aa = g_att + (size_t)h * LL + (size_t)m0 * 512;
    const float* Bv = g_vt + (size_t)h * L * R_DIM + n0;
    float acc[4][4][4] = {};
    const int iters = 512 / 32;
    cpa_A32(As, Aa, 512, tid); cpa_B32(Bs, Bv, R_DIM, tid); cpa_commit();
    cpa_A32(As + 128, Aa + 32, 512, tid);
    cpa_B32(Bs + 32, Bv + (size_t)32 * R_DIM, R_DIM, tid); cpa_commit();
    for (int i = 0; i < iters; i++) {
        cpa_wait<1>();
        __syncthreads();
        comp32(As + (i % 3) * 128, Bs + (i % 3) * 32, acc, wr, wc, lane);
        if (i + 2 < iters) {
            cpa_A32(As + ((i + 2) % 3) * 128, Aa + (i + 2) * 32, 512, tid);
            cpa_B32(Bs + ((i + 2) % 3) * 32, Bv + (size_t)(i + 2) * 32 * R_DIM, R_DIM, tid);
        }
        cpa_commit();
    }
    int t = lane & 3, g = lane >> 2;
    float* outp = g_o + (size_t)h * L * R_DIM;
    #pragma unroll
    for (int mi = 0; mi < 4; mi++) {
        int l = m0 + wr * 64 + mi * 16 + g;
        #pragma unroll
        for (int ni = 0; ni < 4; ni++) {
            int n = n0 + wc * 32 + ni * 8 + t * 2;
            int bb = n >> 5, cc = n & 31;
            const float* sig0 = g_sig + ((size_t)bb * 512 + l) * 128 + h * 32 + cc;
            float2 s0 = *(const float2*)sig0;
            float2 s1 = *(const float2*)(sig0 + 8 * 128);
            *(float2*)(outp + (size_t)l * R_DIM + n) =
                make_float2(tf32f(acc[mi][ni][0] * s0.x), tf32f(acc[mi][ni][1] * s0.y));
            *(float2*)(outp + (size_t)(l + 8) * R_DIM + n) =
                make_float2(tf32f(acc[mi][ni][2] * s1.x), tf32f(acc[mi][ni][3] * s1.y));
        }
    }
}

// ---------------- final: out = g_o @ ow + ob (pipelined) ---------------------
// grid (2048)
__global__ void __launch_bounds__(256, 2) out_mma(const float* __restrict__ ob,
                                                  float* __restrict__ out) {
    extern __shared__ float sp[];
    float (*As)[36] = (float(*)[36])sp;
    float (*Bs)[136] = (float(*)[136])(sp + 3 * 128 * 36);
    int m0 = blockIdx.x * 128;
    int b = m0 >> 9, l0 = m0 & 511;
    int tid = threadIdx.x, lane = tid & 31, wid = tid >> 5;
    int wr = wid >> 2, wc = wid & 3;
    float acc[4][4][4] = {};
    const int iters = 4;
    #define OUT_APTR(i) (g_o + ((size_t)(i) * 512 + l0) * R_DIM + b * 32)
    cpa_A32(As, OUT_APTR(0), R_DIM, tid);
    cpa_B32(Bs, g_wo, 128, tid); cpa_commit();
    cpa_A32(As + 128, OUT_APTR(1), R_DIM, tid);
    cpa_B32(Bs + 32, g_wo + 32 * 128, 128, tid); cpa_commit();
    for (int i = 0; i < iters; i++) {
        cpa_wait<1>();
        __syncthreads();
        comp32(As + (i % 3) * 128, Bs + (i % 3) * 32, acc, wr, wc, lane);
        if (i + 2 < iters) {
            cpa_A32(As + ((i + 2) % 3) * 128, OUT_APTR(i + 2), R_DIM, tid);
            cpa_B32(Bs + ((i + 2) % 3) * 32, g_wo + (size_t)(i + 2) * 32 * 128, 128, tid);
        }
        cpa_commit();
    }
    #undef OUT_APTR
    int t = lane & 3, g = lane >> 2;
    #pragma unroll
    for (int mi = 0; mi < 4; mi++) {
        int r0 = m0 + wr * 64 + mi * 16 + g;
        #pragma unroll
        for (int ni = 0; ni < 4; ni++) {
            int c = wc * 32 + ni * 8 + t * 2;
            float b0 = ob[c], b1 = ob[c + 1];
            *(float2*)(out + (size_t)r0 * 128 + c) =
                make_float2(acc[mi][ni][0] + b0, acc[mi][ni][1] + b1);
            *(float2*)(out + (size_t)(r0 + 8) * 128 + c) =
                make_float2(acc[mi][ni][2] + b0, acc[mi][ni][3] + b1);
        }
    }
}

// ---------------- launcher ---------------------------------------------------
extern "C" void kernel_launch(void* const* d_in, const int* in_sizes, int n_in,
                              void* d_out, int out_size) {
    const float* z_   = (const float*)d_in[0];
    const float* ln_g = (const float*)d_in[1];
    const float* ln_b = (const float*)d_in[2];
    const float* qw   = (const float*)d_in[3];
    const float* qb   = (const float*)d_in[4];
    const float* kw   = (const float*)d_in[5];
    const float* kb   = (const float*)d_in[6];
    const float* vw   = (const float*)d_in[7];
    const float* vb   = (const float*)d_in[8];
    const float* bw   = (const float*)d_in[9];
    const float* bb   = (const float*)d_in[10];
    const float* gw   = (const float*)d_in[11];
    const float* gb   = (const float*)d_in[12];
    const float* ow   = (const float*)d_in[13];
    const float* ob   = (const float*)d_in[14];
    float* out = (float*)d_out;

    cudaFuncSetAttribute(proj_mma, cudaFuncAttributeMaxDynamicSharedMemorySize, DYN_STD);
    cudaFuncSetAttribute(att_mma, cudaFuncAttributeMaxDynamicSharedMemorySize, DYN_ATT);
    cudaFuncSetAttribute(o_mma, cudaFuncAttributeMaxDynamicSharedMemorySize, DYN_STD);
    cudaFuncSetAttribute(out_mma, cudaFuncAttributeMaxDynamicSharedMemorySize, DYN_STD);

    cudaStream_t s2;
    cudaStreamCreate(&s2);
    cudaEvent_t eFork, eJoin;
    cudaEventCreateWithFlags(&eFork, cudaEventDisableTiming);
    cudaEventCreateWithFlags(&eJoin, cudaEventDisableTiming);

    round_w<<<(D * D + 255) / 256, 256>>>(qw, kw, vw, gw, ow);
    ln_bias_kernel<<<M_ROWS / 8, 256>>>(z_, ln_g, ln_b, bw, bb);

    // fork: v/g projections run concurrently with q/k -> att -> softmax
    cudaEventRecord(eFork, 0);
    cudaStreamWaitEvent(s2, eFork, 0);
    proj_mma<<<dim3(2, 2048), 256, DYN_STD, s2>>>(2, qb, kb, vb, gb);  // v, g

    proj_mma<<<dim3(2, 2048), 256, DYN_STD>>>(0, qb, kb, vb, gb);      // q, k
    float scale = 1.0f / (sqrtf((float)CC) * sqrtf((float)L));
    att_mma<<<dim3(2, 4, 32), 256, DYN_ATT>>>();
    softmax2<<<NH * L, 128>>>(scale);

    // join: o_mma needs v (s2) and att probs + sig (s2)
    cudaEventRecord(eJoin, s2);
    cudaStreamWaitEvent(0, eJoin, 0);

    o_mma<<<dim3(4, 128, 4), 256, DYN_STD>>>();
    out_mma<<<2048, 256, DYN_STD>>>(ob, out);

    cudaEventDestroy(eFork);
    cudaEventDestroy(eJoin);
    cudaStreamDestroy(s2);
}